// round 1
// baseline (speedup 1.0000x reference)
#include <cuda_runtime.h>
#include <cuda_bf16.h>
#include <math.h>

// ---------------------------------------------------------------------------
// Problem constants
// ---------------------------------------------------------------------------
#define BATCH 4
#define SEQ   1024
#define DMODEL 512
#define DINNER 2048
#define NHEAD 8
#define DHEAD 64
#define NLAYER 6
#define NTOK (BATCH*SEQ)          // 4096
#define SQRT_D 22.627416997969522f
#define INV_SQRT_DH 0.125f

// ---------------------------------------------------------------------------
// Scratch (device globals: no allocations allowed)
// ---------------------------------------------------------------------------
__device__ float g_h   [NTOK*DMODEL];
__device__ float g_q   [NTOK*DMODEL];
__device__ float g_k   [NTOK*DMODEL];
__device__ float g_v   [NTOK*DMODEL];
__device__ float g_attn[NTOK*DMODEL];
__device__ float g_h1  [NTOK*DMODEL];
__device__ float g_ffn [NTOK*DMODEL];
__device__ float g_mid [NTOK*DINNER];

// ---------------------------------------------------------------------------
// Embedding: h[t,d] = emb[x[t],d]*sqrt(D) + pos[t%SEQ, d]
// ---------------------------------------------------------------------------
__global__ void embed_kernel(const int* __restrict__ x, const float* __restrict__ emb,
                             const float* __restrict__ pos) {
    int idx = blockIdx.x * blockDim.x + threadIdx.x;   // NTOK*DMODEL
    int t = idx >> 9;
    int d = idx & 511;
    int s = t & (SEQ-1);
    int tok = x[t];
    g_h[idx] = emb[(size_t)tok*DMODEL + d] * SQRT_D + pos[(size_t)s*DMODEL + d];
}

// ---------------------------------------------------------------------------
// Tiled SGEMM: C[M,N] = A[M,K] @ B[K,N] + bias[N]  (optional ReLU)
// TILE 128x64x16, 256 threads, 8x4 microtile. M%128==0, N%64==0, K%16==0.
// ---------------------------------------------------------------------------
template<bool RELU>
__global__ void gemm_bias_kernel(const float* __restrict__ A, const float* __restrict__ B,
                                 const float* __restrict__ bias, float* __restrict__ C,
                                 int M, int N, int K) {
    __shared__ float As[16][132];
    __shared__ float Bs[16][68];
    const int tid = threadIdx.x;
    const int tx = tid & 15;          // 0..15 -> 4 cols each
    const int ty = tid >> 4;          // 0..15 -> 8 rows each
    const int m0 = blockIdx.y * 128;
    const int n0 = blockIdx.x * 64;

    float acc[8][4];
    #pragma unroll
    for (int i = 0; i < 8; i++)
        #pragma unroll
        for (int j = 0; j < 4; j++) acc[i][j] = 0.f;

    for (int k0 = 0; k0 < K; k0 += 16) {
        // load A tile (128x16) transposed
        #pragma unroll
        for (int t = 0; t < 2; t++) {
            int fa = tid + t*256;              // [0,512)
            int ar = fa >> 2;                  // row 0..127
            int ak = (fa & 3) * 4;             // k 0,4,8,12
            float4 av = *reinterpret_cast<const float4*>(&A[(size_t)(m0+ar)*K + k0 + ak]);
            As[ak+0][ar] = av.x; As[ak+1][ar] = av.y;
            As[ak+2][ar] = av.z; As[ak+3][ar] = av.w;
        }
        // load B tile (16x64)
        {
            int br = tid >> 4;
            int bn = (tid & 15) * 4;
            float4 bv = *reinterpret_cast<const float4*>(&B[(size_t)(k0+br)*N + n0 + bn]);
            Bs[br][bn+0] = bv.x; Bs[br][bn+1] = bv.y;
            Bs[br][bn+2] = bv.z; Bs[br][bn+3] = bv.w;
        }
        __syncthreads();
        #pragma unroll
        for (int kk = 0; kk < 16; kk++) {
            float a[8], bb[4];
            #pragma unroll
            for (int i = 0; i < 8; i++) a[i] = As[kk][ty*8 + i];
            #pragma unroll
            for (int j = 0; j < 4; j++) bb[j] = Bs[kk][tx*4 + j];
            #pragma unroll
            for (int i = 0; i < 8; i++)
                #pragma unroll
                for (int j = 0; j < 4; j++)
                    acc[i][j] = fmaf(a[i], bb[j], acc[i][j]);
        }
        __syncthreads();
    }
    #pragma unroll
    for (int i = 0; i < 8; i++) {
        int row = m0 + ty*8 + i;
        #pragma unroll
        for (int j = 0; j < 4; j++) {
            int col = n0 + tx*4 + j;
            float v = acc[i][j] + bias[col];
            if (RELU) v = fmaxf(v, 0.f);
            C[(size_t)row*N + col] = v;
        }
    }
}

// ---------------------------------------------------------------------------
// Flash-style relative attention, one (batch*head, 64-query-tile) per block.
//   Srel[i,j] = (j<=i) ? q_i . E[1023-i+j] : 0   (skew trick, derived)
//   logits = (q.k + Srel) * 0.125 ; softmax over ALL keys (non-causal)
// smem: qs(64x65) ks/vs(64x65) es(128x65) ps(64x65) = 83.2 KB dynamic
// ---------------------------------------------------------------------------
__global__ void attention_kernel(const float* __restrict__ q, const float* __restrict__ k,
                                 const float* __restrict__ v, const float* __restrict__ E,
                                 float* __restrict__ out) {
    extern __shared__ float sm[];
    float* qs = sm;                    // 64*65
    float* ks = qs + 64*65;            // 64*65 (reused for V)
    float* es = ks + 64*65;            // 128*65
    float* ps = es + 128*65;           // 64*65

    const int bh = blockIdx.y;         // 0..31
    const int b  = bh >> 3;
    const int h  = bh & 7;
    const int i0 = blockIdx.x * 64;
    const int tid = threadIdx.x;       // 256
    const int il = tid >> 2;           // query row in tile 0..63
    const int cg = tid & 3;            // column group 0..3 (16 cols each)

    const int tok0 = b * SEQ;
    const int hoff = h * DHEAD;

    // load Q tile
    #pragma unroll
    for (int t = 0; t < 4; t++) {
        int f = tid + t*256;           // [0,1024)
        int r = f >> 4, c = (f & 15) * 4;
        float4 qv = *reinterpret_cast<const float4*>(&q[(size_t)(tok0 + i0 + r)*DMODEL + hoff + c]);
        qs[r*65+c] = qv.x; qs[r*65+c+1] = qv.y; qs[r*65+c+2] = qv.z; qs[r*65+c+3] = qv.w;
    }

    float mrow = -1e30f, lrow = 0.f;
    float acc[16];
    #pragma unroll
    for (int d = 0; d < 16; d++) acc[d] = 0.f;

    for (int jt = 0; jt < 16; jt++) {
        const int j0 = jt * 64;
        __syncthreads();               // ks buffer reuse (was V last iter)
        // load K tile
        #pragma unroll
        for (int t = 0; t < 4; t++) {
            int f = tid + t*256;
            int r = f >> 4, c = (f & 15) * 4;
            float4 kv = *reinterpret_cast<const float4*>(&k[(size_t)(tok0 + j0 + r)*DMODEL + hoff + c]);
            ks[r*65+c] = kv.x; ks[r*65+c+1] = kv.y; ks[r*65+c+2] = kv.z; ks[r*65+c+3] = kv.w;
        }
        // load E window: rows m_base .. m_base+127
        const int m_base = 960 - i0 + j0;
        #pragma unroll
        for (int t = 0; t < 8; t++) {
            int f = tid + t*256;       // [0,2048)
            int r = f >> 4, c = (f & 15) * 4;
            int m = m_base + r;
            float4 ev = make_float4(0.f,0.f,0.f,0.f);
            if (m >= 0 && m < SEQ)
                ev = *reinterpret_cast<const float4*>(&E[(size_t)m*DHEAD + c]);
            es[r*65+c] = ev.x; es[r*65+c+1] = ev.y; es[r*65+c+2] = ev.z; es[r*65+c+3] = ev.w;
        }
        __syncthreads();

        // scores: 16 per thread
        float s[16];
        #pragma unroll
        for (int jj = 0; jj < 16; jj++) s[jj] = 0.f;
        #pragma unroll 8
        for (int d = 0; d < 64; d++) {
            float qv = qs[il*65 + d];
            #pragma unroll
            for (int jj = 0; jj < 16; jj++)
                s[jj] = fmaf(qv, ks[(cg*16+jj)*65 + d], s[jj]);
        }
        // relative-position term for j_g <= i_g
        {
            const int ig = i0 + il;
            int lim = ig - j0 - cg*16;              // rel applies for jj <= lim
            if (lim >= 0) {
                int nrel = lim + 1; if (nrel > 16) nrel = 16;
                for (int jj = 0; jj < nrel; jj++) {
                    int ml = 63 - il + cg*16 + jj;  // = (1023-ig+jg) - m_base
                    float r2 = 0.f;
                    #pragma unroll 8
                    for (int d = 0; d < 64; d++)
                        r2 = fmaf(qs[il*65+d], es[ml*65 + d], r2);
                    s[jj] += r2;
                }
            }
        }
        #pragma unroll
        for (int jj = 0; jj < 16; jj++) s[jj] *= INV_SQRT_DH;

        // online softmax update (row spread across 4 consecutive lanes)
        float tmax = s[0];
        #pragma unroll
        for (int jj = 1; jj < 16; jj++) tmax = fmaxf(tmax, s[jj]);
        tmax = fmaxf(tmax, __shfl_xor_sync(0xffffffffu, tmax, 1));
        tmax = fmaxf(tmax, __shfl_xor_sync(0xffffffffu, tmax, 2));
        float mnew = fmaxf(mrow, tmax);
        float alpha = __expf(mrow - mnew);
        float psum = 0.f;
        #pragma unroll
        for (int jj = 0; jj < 16; jj++) {
            float p = __expf(s[jj] - mnew);
            ps[il*65 + cg*16 + jj] = p;
            psum += p;
        }
        psum += __shfl_xor_sync(0xffffffffu, psum, 1);
        psum += __shfl_xor_sync(0xffffffffu, psum, 2);
        lrow = lrow * alpha + psum;
        mrow = mnew;
        #pragma unroll
        for (int d = 0; d < 16; d++) acc[d] *= alpha;

        __syncthreads();
        // load V tile into ks buffer
        #pragma unroll
        for (int t = 0; t < 4; t++) {
            int f = tid + t*256;
            int r = f >> 4, c = (f & 15) * 4;
            float4 vv = *reinterpret_cast<const float4*>(&v[(size_t)(tok0 + j0 + r)*DMODEL + hoff + c]);
            ks[r*65+c] = vv.x; ks[r*65+c+1] = vv.y; ks[r*65+c+2] = vv.z; ks[r*65+c+3] = vv.w;
        }
        __syncthreads();
        // acc += P @ V  (thread owns out dims cg*16..+15 of row il)
        #pragma unroll 4
        for (int kk = 0; kk < 64; kk++) {
            float p = ps[il*65 + kk];
            #pragma unroll
            for (int d = 0; d < 16; d++)
                acc[d] = fmaf(p, ks[kk*65 + cg*16 + d], acc[d]);
        }
    }

    float inv = 1.f / lrow;
    #pragma unroll
    for (int d = 0; d < 16; d++)
        out[(size_t)(tok0 + i0 + il)*DMODEL + hoff + cg*16 + d] = acc[d] * inv;
}

// ---------------------------------------------------------------------------
// y = LayerNorm(a + b) * scale + bias   (one token per block, 128 threads)
// ---------------------------------------------------------------------------
__global__ void add_ln_kernel(const float* __restrict__ a, const float* __restrict__ b,
                              const float* __restrict__ scale, const float* __restrict__ bias,
                              float* __restrict__ y) {
    const int t = blockIdx.x;
    const int tid = threadIdx.x;       // 128
    float x[4];
    float sum = 0.f;
    #pragma unroll
    for (int i = 0; i < 4; i++) {
        int d = tid + i*128;
        x[i] = a[(size_t)t*DMODEL + d] + b[(size_t)t*DMODEL + d];
        sum += x[i];
    }
    __shared__ float red[4];
    #pragma unroll
    for (int o = 16; o > 0; o >>= 1) sum += __shfl_xor_sync(0xffffffffu, sum, o);
    if ((tid & 31) == 0) red[tid >> 5] = sum;
    __syncthreads();
    sum = red[0] + red[1] + red[2] + red[3];
    const float mu = sum * (1.f/512.f);
    float vs = 0.f;
    #pragma unroll
    for (int i = 0; i < 4; i++) { float dd = x[i] - mu; vs = fmaf(dd, dd, vs); }
    #pragma unroll
    for (int o = 16; o > 0; o >>= 1) vs += __shfl_xor_sync(0xffffffffu, vs, o);
    __shared__ float red2[4];
    if ((tid & 31) == 0) red2[tid >> 5] = vs;
    __syncthreads();
    vs = red2[0] + red2[1] + red2[2] + red2[3];
    const float rstd = rsqrtf(vs * (1.f/512.f) + 1e-6f);
    #pragma unroll
    for (int i = 0; i < 4; i++) {
        int d = tid + i*128;
        y[(size_t)t*DMODEL + d] = (x[i] - mu) * rstd * scale[d] + bias[d];
    }
}

// ---------------------------------------------------------------------------
// out[b,o] = tanh(h[b,0,:] . Wf[:,o] + bf[o])   (one warp per (b,o))
// ---------------------------------------------------------------------------
__global__ void head_kernel(const float* __restrict__ Wf, const float* __restrict__ bf,
                            float* __restrict__ out) {
    const int w = threadIdx.x >> 5;    // 0..7
    const int lane = threadIdx.x & 31;
    const int b = w >> 1, o = w & 1;
    const float* hr = g_h + (size_t)b*SEQ*DMODEL;   // token s=0
    float sum = 0.f;
    #pragma unroll
    for (int d = lane; d < DMODEL; d += 32)
        sum = fmaf(hr[d], Wf[d*2 + o], sum);
    #pragma unroll
    for (int off = 16; off > 0; off >>= 1) sum += __shfl_xor_sync(0xffffffffu, sum, off);
    if (lane == 0) out[b*2 + o] = tanhf(sum + bf[o]);
}

// ---------------------------------------------------------------------------
// Launch
// ---------------------------------------------------------------------------
#define ATT_SMEM ((64*65*3 + 128*65) * sizeof(float))   // 83200 B

extern "C" void kernel_launch(void* const* d_in, const int* in_sizes, int n_in,
                              void* d_out, int out_size) {
    const int*   x    = (const int*)  d_in[0];
    const float* emb  = (const float*)d_in[1];
    const float* pos  = (const float*)d_in[2];
    const float* Wq   = (const float*)d_in[3];
    const float* bq   = (const float*)d_in[4];
    const float* Wk   = (const float*)d_in[5];
    const float* bk   = (const float*)d_in[6];
    const float* Wv   = (const float*)d_in[7];
    const float* bv   = (const float*)d_in[8];
    const float* Wo   = (const float*)d_in[9];
    const float* bo   = (const float*)d_in[10];
    const float* E    = (const float*)d_in[11];
    const float* W1   = (const float*)d_in[12];
    const float* b1   = (const float*)d_in[13];
    const float* W2   = (const float*)d_in[14];
    const float* b2   = (const float*)d_in[15];
    const float* ln1s = (const float*)d_in[16];
    const float* ln1b = (const float*)d_in[17];
    const float* ln2s = (const float*)d_in[18];
    const float* ln2b = (const float*)d_in[19];
    const float* Wf   = (const float*)d_in[20];
    const float* bf   = (const float*)d_in[21];
    float* out = (float*)d_out;

    float *h, *qb, *kb, *vb, *attn, *h1, *mid, *ffn;
    cudaGetSymbolAddress((void**)&h,    g_h);
    cudaGetSymbolAddress((void**)&qb,   g_q);
    cudaGetSymbolAddress((void**)&kb,   g_k);
    cudaGetSymbolAddress((void**)&vb,   g_v);
    cudaGetSymbolAddress((void**)&attn, g_attn);
    cudaGetSymbolAddress((void**)&h1,   g_h1);
    cudaGetSymbolAddress((void**)&mid,  g_mid);
    cudaGetSymbolAddress((void**)&ffn,  g_ffn);

    cudaFuncSetAttribute(attention_kernel,
                         cudaFuncAttributeMaxDynamicSharedMemorySize, (int)ATT_SMEM);

    embed_kernel<<<NTOK*DMODEL/256, 256>>>(x, emb, pos);

    for (int l = 0; l < NLAYER; l++) {
        const size_t wl = (size_t)l * DMODEL * DMODEL;
        gemm_bias_kernel<false><<<dim3(8,32), 256>>>(h, Wq + wl, bq + l*DMODEL, qb, NTOK, DMODEL, DMODEL);
        gemm_bias_kernel<false><<<dim3(8,32), 256>>>(h, Wk + wl, bk + l*DMODEL, kb, NTOK, DMODEL, DMODEL);
        gemm_bias_kernel<false><<<dim3(8,32), 256>>>(h, Wv + wl, bv + l*DMODEL, vb, NTOK, DMODEL, DMODEL);

        attention_kernel<<<dim3(16,32), 256, ATT_SMEM>>>(qb, kb, vb, E + (size_t)l*SEQ*DHEAD, attn);

        gemm_bias_kernel<false><<<dim3(8,32), 256>>>(attn, Wo + wl, bo + l*DMODEL, ffn, NTOK, DMODEL, DMODEL);
        add_ln_kernel<<<NTOK, 128>>>(ffn, h, ln1s + l*DMODEL, ln1b + l*DMODEL, h1);

        gemm_bias_kernel<true ><<<dim3(32,32), 256>>>(h1, W1 + (size_t)l*DMODEL*DINNER, b1 + l*DINNER, mid, NTOK, DINNER, DMODEL);
        gemm_bias_kernel<false><<<dim3(8,32),  256>>>(mid, W2 + (size_t)l*DINNER*DMODEL, b2 + l*DMODEL, ffn, NTOK, DMODEL, DINNER);
        add_ln_kernel<<<NTOK, 128>>>(h1, ffn, ln2s + l*DMODEL, ln2b + l*DMODEL, h);
    }

    head_kernel<<<1, 256>>>(Wf, bf, out);
}

// round 2
// speedup vs baseline: 1.9772x; 1.9772x over previous
#include <cuda_runtime.h>
#include <cuda_bf16.h>
#include <math.h>

// ---------------------------------------------------------------------------
// Problem constants
// ---------------------------------------------------------------------------
#define BATCH 4
#define SEQ   1024
#define DMODEL 512
#define DINNER 2048
#define NHEAD 8
#define DHEAD 64
#define NLAYER 6
#define NTOK (BATCH*SEQ)          // 4096
#define SQRT_D 22.627416997969522f
#define INV_SQRT_DH 0.125f

// ---------------------------------------------------------------------------
// Scratch (device globals: no allocations allowed)
// ---------------------------------------------------------------------------
__device__ float g_h   [NTOK*DMODEL];
__device__ float g_q   [NTOK*DMODEL];
__device__ float g_k   [NTOK*DMODEL];
__device__ float g_v   [NTOK*DMODEL];
__device__ float g_attn[NTOK*DMODEL];
__device__ float g_h1  [NTOK*DMODEL];
__device__ float g_ffn [NTOK*DMODEL];
__device__ float g_mid [NTOK*DINNER];
__device__ float g_sk  [32u*1024u*1024u];   // SK[bh][i][j] = q_i . E[1023-i+j], j<=i

// ---------------------------------------------------------------------------
// Embedding: h[t,d] = emb[x[t],d]*sqrt(D) + pos[t%SEQ, d]
// ---------------------------------------------------------------------------
__global__ void embed_kernel(const int* __restrict__ x, const float* __restrict__ emb,
                             const float* __restrict__ pos) {
    int idx = blockIdx.x * blockDim.x + threadIdx.x;   // NTOK*DMODEL
    int t = idx >> 9;
    int d = idx & 511;
    int s = t & (SEQ-1);
    int tok = x[t];
    g_h[idx] = emb[(size_t)tok*DMODEL + d] * SQRT_D + pos[(size_t)s*DMODEL + d];
}

// ---------------------------------------------------------------------------
// Tiled SGEMM: C[M,N] = A[M,K] @ B[K,N] + bias[N]  (optional ReLU)
// TILE 128x64x16, 256 threads, 8x4 microtile.
// ---------------------------------------------------------------------------
template<bool RELU>
__device__ __forceinline__ void gemm_body(const float* __restrict__ A, const float* __restrict__ B,
                                          const float* __restrict__ bias, float* __restrict__ C,
                                          int M, int N, int K) {
    __shared__ float As[16][132];
    __shared__ float Bs[16][68];
    const int tid = threadIdx.x;
    const int tx = tid & 15;
    const int ty = tid >> 4;
    const int m0 = blockIdx.y * 128;
    const int n0 = blockIdx.x * 64;

    float acc[8][4];
    #pragma unroll
    for (int i = 0; i < 8; i++)
        #pragma unroll
        for (int j = 0; j < 4; j++) acc[i][j] = 0.f;

    for (int k0 = 0; k0 < K; k0 += 16) {
        #pragma unroll
        for (int t = 0; t < 2; t++) {
            int fa = tid + t*256;
            int ar = fa >> 2;
            int ak = (fa & 3) * 4;
            float4 av = *reinterpret_cast<const float4*>(&A[(size_t)(m0+ar)*K + k0 + ak]);
            As[ak+0][ar] = av.x; As[ak+1][ar] = av.y;
            As[ak+2][ar] = av.z; As[ak+3][ar] = av.w;
        }
        {
            int br = tid >> 4;
            int bn = (tid & 15) * 4;
            float4 bv = *reinterpret_cast<const float4*>(&B[(size_t)(k0+br)*N + n0 + bn]);
            Bs[br][bn+0] = bv.x; Bs[br][bn+1] = bv.y;
            Bs[br][bn+2] = bv.z; Bs[br][bn+3] = bv.w;
        }
        __syncthreads();
        #pragma unroll
        for (int kk = 0; kk < 16; kk++) {
            float a[8], bb[4];
            #pragma unroll
            for (int i = 0; i < 8; i++) a[i] = As[kk][ty*8 + i];
            #pragma unroll
            for (int j = 0; j < 4; j++) bb[j] = Bs[kk][tx*4 + j];
            #pragma unroll
            for (int i = 0; i < 8; i++)
                #pragma unroll
                for (int j = 0; j < 4; j++)
                    acc[i][j] = fmaf(a[i], bb[j], acc[i][j]);
        }
        __syncthreads();
    }
    #pragma unroll
    for (int i = 0; i < 8; i++) {
        int row = m0 + ty*8 + i;
        #pragma unroll
        for (int j = 0; j < 4; j++) {
            int col = n0 + tx*4 + j;
            float v = acc[i][j] + bias[col];
            if (RELU) v = fmaxf(v, 0.f);
            C[(size_t)row*N + col] = v;
        }
    }
}

template<bool RELU>
__global__ void gemm_bias_kernel(const float* __restrict__ A, const float* __restrict__ B,
                                 const float* __restrict__ bias, float* __restrict__ C,
                                 int M, int N, int K) {
    gemm_body<RELU>(A, B, bias, C, M, N, K);
}

// QKV fused: blockIdx.z picks which projection
__global__ void gemm_qkv_kernel(const float* __restrict__ A,
                                const float* __restrict__ B0, const float* __restrict__ B1, const float* __restrict__ B2,
                                const float* __restrict__ b0, const float* __restrict__ b1, const float* __restrict__ b2,
                                float* __restrict__ C0, float* __restrict__ C1, float* __restrict__ C2,
                                int M, int N, int K) {
    const int z = blockIdx.z;
    const float* B = (z == 0) ? B0 : (z == 1) ? B1 : B2;
    const float* bi = (z == 0) ? b0 : (z == 1) ? b1 : b2;
    float* C = (z == 0) ? C0 : (z == 1) ? C1 : C2;
    gemm_body<false>(A, B, bi, C, M, N, K);
}

// ---------------------------------------------------------------------------
// QE-skew precompute: SK[bh][i][j] = q_i . E[1023-i+j]  (only j in [0, i])
// One block per (bh, 64-row i-tile). Loops over 128-row E tiles.
// smem (dynamic): qsT[64][68] (d-major), esT[64][136] (d-major)  = 52224 B
// ---------------------------------------------------------------------------
#define QESK_SMEM ((64*68 + 64*136) * sizeof(float))

__global__ void qe_skew_kernel(const float* __restrict__ q, const float* __restrict__ E,
                               float* __restrict__ SK) {
    extern __shared__ float sm[];
    float* qsT = sm;             // [d][i] stride 68
    float* esT = qsT + 64*68;    // [d][m_local] stride 136

    const int bh = blockIdx.y;            // 0..31
    const int b  = bh >> 3;
    const int h  = bh & 7;
    const int i0 = blockIdx.x * 64;
    const int tid = threadIdx.x;          // 256
    const int r = tid >> 4;               // row group: rows r*4..r*4+3
    const int c = tid & 15;               // col group: cols c*8..c*8+7
    const int tok0 = b * SEQ;
    const int hoff = h * DHEAD;

    // load Q tile transposed
    #pragma unroll
    for (int t = 0; t < 4; t++) {
        int f = tid + t*256;              // [0,1024)
        int i = f >> 4, d4 = (f & 15) * 4;
        float4 qv = *reinterpret_cast<const float4*>(&q[(size_t)(tok0 + i0 + i)*DMODEL + hoff + d4]);
        qsT[(d4+0)*68 + i] = qv.x; qsT[(d4+1)*68 + i] = qv.y;
        qsT[(d4+2)*68 + i] = qv.z; qsT[(d4+3)*68 + i] = qv.w;
    }

    const int mt_lo = ((960 - i0) / 128) * 128;   // first E tile containing any needed m

    float* dst_base = SK + ((size_t)bh << 20);

    for (int mt = mt_lo; mt < 1024; mt += 128) {
        __syncthreads();
        // load E tile transposed: esT[d][ml]
        #pragma unroll
        for (int t = 0; t < 8; t++) {
            int f = tid + t*256;          // [0,2048)
            int ml = f >> 4, d4 = (f & 15) * 4;
            float4 ev = *reinterpret_cast<const float4*>(&E[(size_t)(mt + ml)*DHEAD + d4]);
            esT[(d4+0)*136 + ml] = ev.x; esT[(d4+1)*136 + ml] = ev.y;
            esT[(d4+2)*136 + ml] = ev.z; esT[(d4+3)*136 + ml] = ev.w;
        }
        __syncthreads();

        float s[4][8];
        #pragma unroll
        for (int i = 0; i < 4; i++)
            #pragma unroll
            for (int j = 0; j < 8; j++) s[i][j] = 0.f;

        #pragma unroll 16
        for (int d = 0; d < 64; d++) {
            float4 a  = *reinterpret_cast<const float4*>(&qsT[d*68 + r*4]);
            float4 e0 = *reinterpret_cast<const float4*>(&esT[d*136 + c*8]);
            float4 e1 = *reinterpret_cast<const float4*>(&esT[d*136 + c*8 + 4]);
            float av[4] = {a.x, a.y, a.z, a.w};
            float ev[8] = {e0.x, e0.y, e0.z, e0.w, e1.x, e1.y, e1.z, e1.w};
            #pragma unroll
            for (int i = 0; i < 4; i++)
                #pragma unroll
                for (int j = 0; j < 8; j++)
                    s[i][j] = fmaf(av[i], ev[j], s[i][j]);
        }

        // scatter to skewed coords: j = m - 1023 + i  (j <= i always here)
        #pragma unroll
        for (int rr = 0; rr < 4; rr++) {
            int ig = i0 + r*4 + rr;
            int jb = mt + c*8 - 1023 + ig;
            float* dst = dst_base + ((size_t)ig << 10);
            #pragma unroll
            for (int cc = 0; cc < 8; cc++) {
                int j = jb + cc;
                if (j >= 0) dst[j] = s[rr][cc];
            }
        }
    }
}

// ---------------------------------------------------------------------------
// Flash attention with precomputed skewed rel term.
//   logits = (q.k + SK[i][j]*(j<=i)) * 0.125 ; softmax over ALL keys
// 4x4 register microtiles, vectorized LDS on transposed tiles.
// smem (dynamic): qsT[64][68], ksT[64][68], vs[64][68], psT[64][68] = 69632 B
// ---------------------------------------------------------------------------
#define ATT_SMEM (4 * 64*68 * sizeof(float))

__global__ void attention_kernel(const float* __restrict__ q, const float* __restrict__ k,
                                 const float* __restrict__ v, const float* __restrict__ SK,
                                 float* __restrict__ out) {
    extern __shared__ float sm[];
    float* qsT = sm;             // [d][i]
    float* ksT = qsT + 64*68;    // [d][j]
    float* vs  = ksT + 64*68;    // [j][d]
    float* psT = vs  + 64*68;    // [j][i]

    const int bh = blockIdx.y;
    const int b  = bh >> 3;
    const int h  = bh & 7;
    const int i0 = blockIdx.x * 64;
    const int tid = threadIdx.x;       // 256
    const int r = tid >> 4;            // rows r*4..r*4+3
    const int c = tid & 15;            // cols c*4..c*4+3
    const int tok0 = b * SEQ;
    const int hoff = h * DHEAD;

    // load Q transposed
    #pragma unroll
    for (int t = 0; t < 4; t++) {
        int f = tid + t*256;
        int i = f >> 4, d4 = (f & 15) * 4;
        float4 qv = *reinterpret_cast<const float4*>(&q[(size_t)(tok0 + i0 + i)*DMODEL + hoff + d4]);
        qsT[(d4+0)*68 + i] = qv.x; qsT[(d4+1)*68 + i] = qv.y;
        qsT[(d4+2)*68 + i] = qv.z; qsT[(d4+3)*68 + i] = qv.w;
    }

    float m_i[4], l_i[4], acc[4][4];
    #pragma unroll
    for (int i = 0; i < 4; i++) {
        m_i[i] = -1e30f; l_i[i] = 0.f;
        #pragma unroll
        for (int j = 0; j < 4; j++) acc[i][j] = 0.f;
    }

    const float* sk_base = SK + ((size_t)bh << 20);

    for (int jt = 0; jt < 16; jt++) {
        const int j0 = jt * 64;
        __syncthreads();
        // load K transposed + V natural
        #pragma unroll
        for (int t = 0; t < 4; t++) {
            int f = tid + t*256;
            int j = f >> 4, d4 = (f & 15) * 4;
            float4 kv = *reinterpret_cast<const float4*>(&k[(size_t)(tok0 + j0 + j)*DMODEL + hoff + d4]);
            ksT[(d4+0)*68 + j] = kv.x; ksT[(d4+1)*68 + j] = kv.y;
            ksT[(d4+2)*68 + j] = kv.z; ksT[(d4+3)*68 + j] = kv.w;
            float4 vv = *reinterpret_cast<const float4*>(&v[(size_t)(tok0 + j0 + j)*DMODEL + hoff + d4]);
            *reinterpret_cast<float4*>(&vs[j*68 + d4]) = vv;
        }
        __syncthreads();

        // scores (QK)
        float s[4][4];
        #pragma unroll
        for (int i = 0; i < 4; i++)
            #pragma unroll
            for (int j = 0; j < 4; j++) s[i][j] = 0.f;

        #pragma unroll 16
        for (int d = 0; d < 64; d++) {
            float4 a  = *reinterpret_cast<const float4*>(&qsT[d*68 + r*4]);
            float4 bb = *reinterpret_cast<const float4*>(&ksT[d*68 + c*4]);
            float av[4] = {a.x, a.y, a.z, a.w};
            float bv[4] = {bb.x, bb.y, bb.z, bb.w};
            #pragma unroll
            for (int i = 0; i < 4; i++)
                #pragma unroll
                for (int j = 0; j < 4; j++)
                    s[i][j] = fmaf(av[i], bv[j], s[i][j]);
        }

        // add precomputed rel term (j <= i)
        #pragma unroll
        for (int rr = 0; rr < 4; rr++) {
            int ig = i0 + r*4 + rr;
            int jb = j0 + c*4;
            const float* skp = sk_base + ((size_t)ig << 10) + jb;
            if (jb + 3 <= ig) {
                float4 sk4 = *reinterpret_cast<const float4*>(skp);
                s[rr][0] += sk4.x; s[rr][1] += sk4.y; s[rr][2] += sk4.z; s[rr][3] += sk4.w;
            } else if (jb <= ig) {
                #pragma unroll
                for (int cc = 0; cc < 4; cc++)
                    if (jb + cc <= ig) s[rr][cc] += skp[cc];
            }
        }

        // scale + online softmax (row spread across the 16 c-threads)
        #pragma unroll
        for (int rr = 0; rr < 4; rr++) {
            float mx = s[rr][0];
            #pragma unroll
            for (int cc = 1; cc < 4; cc++) mx = fmaxf(mx, s[rr][cc] );
            // NB: scale all 4 first for numerical match simplicity
            mx *= INV_SQRT_DH;
            // reduce over 16-lane group
            mx = fmaxf(mx, __shfl_xor_sync(0xffffffffu, mx, 1));
            mx = fmaxf(mx, __shfl_xor_sync(0xffffffffu, mx, 2));
            mx = fmaxf(mx, __shfl_xor_sync(0xffffffffu, mx, 4));
            mx = fmaxf(mx, __shfl_xor_sync(0xffffffffu, mx, 8));
            float mn = fmaxf(m_i[rr], mx);
            float alpha = __expf(m_i[rr] - mn);
            float psum = 0.f;
            #pragma unroll
            for (int cc = 0; cc < 4; cc++) {
                float p = __expf(s[rr][cc] * INV_SQRT_DH - mn);
                psT[(c*4+cc)*68 + r*4 + rr] = p;
                psum += p;
            }
            psum += __shfl_xor_sync(0xffffffffu, psum, 1);
            psum += __shfl_xor_sync(0xffffffffu, psum, 2);
            psum += __shfl_xor_sync(0xffffffffu, psum, 4);
            psum += __shfl_xor_sync(0xffffffffu, psum, 8);
            l_i[rr] = l_i[rr] * alpha + psum;
            m_i[rr] = mn;
            #pragma unroll
            for (int cc = 0; cc < 4; cc++) acc[rr][cc] *= alpha;
        }
        __syncthreads();

        // PV: acc[rr][cc] += sum_kk P[kk][row rr] * V[kk][dh cc]
        #pragma unroll 8
        for (int kk = 0; kk < 64; kk++) {
            float4 p  = *reinterpret_cast<const float4*>(&psT[kk*68 + r*4]);
            float4 vv = *reinterpret_cast<const float4*>(&vs[kk*68 + c*4]);
            float pv[4] = {p.x, p.y, p.z, p.w};
            float vvv[4] = {vv.x, vv.y, vv.z, vv.w};
            #pragma unroll
            for (int i = 0; i < 4; i++)
                #pragma unroll
                for (int j = 0; j < 4; j++)
                    acc[i][j] = fmaf(pv[i], vvv[j], acc[i][j]);
        }
    }

    #pragma unroll
    for (int rr = 0; rr < 4; rr++) {
        float inv = 1.f / l_i[rr];
        float4 o = make_float4(acc[rr][0]*inv, acc[rr][1]*inv, acc[rr][2]*inv, acc[rr][3]*inv);
        *reinterpret_cast<float4*>(&out[(size_t)(tok0 + i0 + r*4 + rr)*DMODEL + hoff + c*4]) = o;
    }
}

// ---------------------------------------------------------------------------
// y = LayerNorm(a + b) * scale + bias   (one token per block, 128 threads)
// ---------------------------------------------------------------------------
__global__ void add_ln_kernel(const float* __restrict__ a, const float* __restrict__ b,
                              const float* __restrict__ scale, const float* __restrict__ bias,
                              float* __restrict__ y) {
    const int t = blockIdx.x;
    const int tid = threadIdx.x;       // 128
    float x[4];
    float sum = 0.f;
    #pragma unroll
    for (int i = 0; i < 4; i++) {
        int d = tid + i*128;
        x[i] = a[(size_t)t*DMODEL + d] + b[(size_t)t*DMODEL + d];
        sum += x[i];
    }
    __shared__ float red[4];
    #pragma unroll
    for (int o = 16; o > 0; o >>= 1) sum += __shfl_xor_sync(0xffffffffu, sum, o);
    if ((tid & 31) == 0) red[tid >> 5] = sum;
    __syncthreads();
    sum = red[0] + red[1] + red[2] + red[3];
    const float mu = sum * (1.f/512.f);
    float vs = 0.f;
    #pragma unroll
    for (int i = 0; i < 4; i++) { float dd = x[i] - mu; vs = fmaf(dd, dd, vs); }
    #pragma unroll
    for (int o = 16; o > 0; o >>= 1) vs += __shfl_xor_sync(0xffffffffu, vs, o);
    __shared__ float red2[4];
    if ((tid & 31) == 0) red2[tid >> 5] = vs;
    __syncthreads();
    vs = red2[0] + red2[1] + red2[2] + red2[3];
    const float rstd = rsqrtf(vs * (1.f/512.f) + 1e-6f);
    #pragma unroll
    for (int i = 0; i < 4; i++) {
        int d = tid + i*128;
        y[(size_t)t*DMODEL + d] = (x[i] - mu) * rstd * scale[d] + bias[d];
    }
}

// ---------------------------------------------------------------------------
// out[b,o] = tanh(h[b,0,:] . Wf[:,o] + bf[o])   (one warp per (b,o))
// ---------------------------------------------------------------------------
__global__ void head_kernel(const float* __restrict__ Wf, const float* __restrict__ bf,
                            float* __restrict__ out) {
    const int w = threadIdx.x >> 5;
    const int lane = threadIdx.x & 31;
    const int b = w >> 1, o = w & 1;
    const float* hr = g_h + (size_t)b*SEQ*DMODEL;   // token s=0
    float sum = 0.f;
    #pragma unroll
    for (int d = lane; d < DMODEL; d += 32)
        sum = fmaf(hr[d], Wf[d*2 + o], sum);
    #pragma unroll
    for (int off = 16; off > 0; off >>= 1) sum += __shfl_xor_sync(0xffffffffu, sum, off);
    if (lane == 0) out[b*2 + o] = tanhf(sum + bf[o]);
}

// ---------------------------------------------------------------------------
// Launch
// ---------------------------------------------------------------------------
extern "C" void kernel_launch(void* const* d_in, const int* in_sizes, int n_in,
                              void* d_out, int out_size) {
    const int*   x    = (const int*)  d_in[0];
    const float* emb  = (const float*)d_in[1];
    const float* pos  = (const float*)d_in[2];
    const float* Wq   = (const float*)d_in[3];
    const float* bq   = (const float*)d_in[4];
    const float* Wk   = (const float*)d_in[5];
    const float* bk   = (const float*)d_in[6];
    const float* Wv   = (const float*)d_in[7];
    const float* bv   = (const float*)d_in[8];
    const float* Wo   = (const float*)d_in[9];
    const float* bo   = (const float*)d_in[10];
    const float* E    = (const float*)d_in[11];
    const float* W1   = (const float*)d_in[12];
    const float* b1   = (const float*)d_in[13];
    const float* W2   = (const float*)d_in[14];
    const float* b2   = (const float*)d_in[15];
    const float* ln1s = (const float*)d_in[16];
    const float* ln1b = (const float*)d_in[17];
    const float* ln2s = (const float*)d_in[18];
    const float* ln2b = (const float*)d_in[19];
    const float* Wf   = (const float*)d_in[20];
    const float* bf   = (const float*)d_in[21];
    float* out = (float*)d_out;

    float *h, *qb, *kb, *vb, *attn, *h1, *mid, *ffn, *sk;
    cudaGetSymbolAddress((void**)&h,    g_h);
    cudaGetSymbolAddress((void**)&qb,   g_q);
    cudaGetSymbolAddress((void**)&kb,   g_k);
    cudaGetSymbolAddress((void**)&vb,   g_v);
    cudaGetSymbolAddress((void**)&attn, g_attn);
    cudaGetSymbolAddress((void**)&h1,   g_h1);
    cudaGetSymbolAddress((void**)&mid,  g_mid);
    cudaGetSymbolAddress((void**)&ffn,  g_ffn);
    cudaGetSymbolAddress((void**)&sk,   g_sk);

    cudaFuncSetAttribute(attention_kernel,
                         cudaFuncAttributeMaxDynamicSharedMemorySize, (int)ATT_SMEM);
    cudaFuncSetAttribute(qe_skew_kernel,
                         cudaFuncAttributeMaxDynamicSharedMemorySize, (int)QESK_SMEM);

    embed_kernel<<<NTOK*DMODEL/256, 256>>>(x, emb, pos);

    for (int l = 0; l < NLAYER; l++) {
        const size_t wl = (size_t)l * DMODEL * DMODEL;

        gemm_qkv_kernel<<<dim3(8,32,3), 256>>>(h,
            Wq + wl, Wk + wl, Wv + wl,
            bq + l*DMODEL, bk + l*DMODEL, bv + l*DMODEL,
            qb, kb, vb, NTOK, DMODEL, DMODEL);

        qe_skew_kernel<<<dim3(16,32), 256, QESK_SMEM>>>(qb, E + (size_t)l*SEQ*DHEAD, sk);

        attention_kernel<<<dim3(16,32), 256, ATT_SMEM>>>(qb, kb, vb, sk, attn);

        gemm_bias_kernel<false><<<dim3(8,32), 256>>>(attn, Wo + wl, bo + l*DMODEL, ffn, NTOK, DMODEL, DMODEL);
        add_ln_kernel<<<NTOK, 128>>>(ffn, h, ln1s + l*DMODEL, ln1b + l*DMODEL, h1);

        gemm_bias_kernel<true ><<<dim3(32,32), 256>>>(h1, W1 + (size_t)l*DMODEL*DINNER, b1 + l*DINNER, mid, NTOK, DINNER, DMODEL);
        gemm_bias_kernel<false><<<dim3(8,32),  256>>>(mid, W2 + (size_t)l*DINNER*DMODEL, b2 + l*DMODEL, ffn, NTOK, DMODEL, DINNER);
        add_ln_kernel<<<NTOK, 128>>>(h1, ffn, ln2s + l*DMODEL, ln2b + l*DMODEL, h);
    }

    head_kernel<<<1, 256>>>(Wf, bf, out);
}

// round 4
// speedup vs baseline: 2.5933x; 1.3116x over previous
#include <cuda_runtime.h>
#include <cuda_bf16.h>
#include <math.h>
#include <stdint.h>

// ---------------------------------------------------------------------------
// Problem constants
// ---------------------------------------------------------------------------
#define BATCH 4
#define SEQ   1024
#define DMODEL 512
#define DINNER 2048
#define NHEAD 8
#define DHEAD 64
#define NLAYER 6
#define NTOK (BATCH*SEQ)          // 4096
#define SQRT_D 22.627416997969522f
#define INV_SQRT_DH 0.125f

// ---------------------------------------------------------------------------
// Scratch (device globals: no allocations allowed)
// ---------------------------------------------------------------------------
__device__ float g_h   [NTOK*DMODEL];
__device__ float g_q   [NTOK*DMODEL];
__device__ float g_k   [NTOK*DMODEL];
__device__ float g_v   [NTOK*DMODEL];
__device__ float g_attn[NTOK*DMODEL];
__device__ float g_h1  [NTOK*DMODEL];
__device__ float g_ffn [NTOK*DMODEL];
__device__ float g_mid [NTOK*DINNER];
__device__ float g_sk  [32u*1024u*1024u];   // SK[bh][i][j] = q_i . E[1023-i+j], j<=i

// bf16 split operands
__device__ __nv_bfloat16 g_act_hi[NTOK*DINNER];
__device__ __nv_bfloat16 g_act_lo[NTOK*DINNER];
__device__ __nv_bfloat16 g_w4_hi[NLAYER*4*DMODEL*DMODEL];   // q,k,v,o transposed [N,K]
__device__ __nv_bfloat16 g_w4_lo[NLAYER*4*DMODEL*DMODEL];
__device__ __nv_bfloat16 g_w1_hi[NLAYER*DINNER*DMODEL];     // W1^T [2048,512]
__device__ __nv_bfloat16 g_w1_lo[NLAYER*DINNER*DMODEL];
__device__ __nv_bfloat16 g_w2_hi[NLAYER*DMODEL*DINNER];     // W2^T [512,2048]
__device__ __nv_bfloat16 g_w2_lo[NLAYER*DMODEL*DINNER];

// ---------------------------------------------------------------------------
// PTX helpers (base-target only: ldmatrix / mma.sync / cp.async)
// ---------------------------------------------------------------------------
__device__ __forceinline__ uint32_t smem_u32(const void* p) {
    uint32_t a;
    asm("{ .reg .u64 t; cvta.to.shared.u64 t, %1; cvt.u32.u64 %0, t; }" : "=r"(a) : "l"(p));
    return a;
}

__device__ __forceinline__ void cp_async16(uint32_t dst, const void* src) {
    asm volatile("cp.async.cg.shared.global [%0], [%1], 16;" :: "r"(dst), "l"(src));
}
#define CP_COMMIT() asm volatile("cp.async.commit_group;" ::: "memory")
#define CP_WAIT(N)  asm volatile("cp.async.wait_group %0;" :: "n"(N) : "memory")

__device__ __forceinline__ void ldm_x4(uint32_t& r0, uint32_t& r1, uint32_t& r2, uint32_t& r3,
                                       uint32_t addr) {
    asm volatile("ldmatrix.sync.aligned.m8n8.x4.shared.b16 {%0,%1,%2,%3}, [%4];"
                 : "=r"(r0), "=r"(r1), "=r"(r2), "=r"(r3) : "r"(addr));
}
__device__ __forceinline__ void ldm_x2(uint32_t& r0, uint32_t& r1, uint32_t addr) {
    asm volatile("ldmatrix.sync.aligned.m8n8.x2.shared.b16 {%0,%1}, [%2];"
                 : "=r"(r0), "=r"(r1) : "r"(addr));
}

__device__ __forceinline__ void mma_bf16(float& c0, float& c1, float& c2, float& c3,
                                         uint32_t a0, uint32_t a1, uint32_t a2, uint32_t a3,
                                         uint32_t b0, uint32_t b1) {
    asm volatile(
        "mma.sync.aligned.m16n8k16.row.col.f32.bf16.bf16.f32 "
        "{%0,%1,%2,%3}, {%4,%5,%6,%7}, {%8,%9}, {%0,%1,%2,%3};"
        : "+f"(c0), "+f"(c1), "+f"(c2), "+f"(c3)
        : "r"(a0), "r"(a1), "r"(a2), "r"(a3), "r"(b0), "r"(b1));
}

// ---------------------------------------------------------------------------
// Tensor-core GEMM (mma.sync): C[M,N] = (Ahi+Alo)[M,K] @ (Bhi+Blo)^T[N,K] + bias
// bf16x3 split: hi*hi + hi*lo + lo*hi accumulated in fp32 fragments.
// CTA tile 128x128, 8 warps (2x4) of 64x32, BK=32, 3-stage cp.async pipeline.
// smem row stride 80B (32 halves + 8 pad) -> conflict-free ldmatrix.
// ---------------------------------------------------------------------------
#define STAGE_BYTES (2*128*80)          // A tile + B tile, one stage
#define MMA_SMEM    (3*STAGE_BYTES)     // 61440 B

template<bool RELU>
__device__ __forceinline__ void mma_gemm_body(
    const __nv_bfloat16* __restrict__ Ahi, const __nv_bfloat16* __restrict__ Alo,
    const __nv_bfloat16* __restrict__ Bhi, const __nv_bfloat16* __restrict__ Blo,
    const float* __restrict__ bias, float* __restrict__ C, int M, int N, int K)
{
    extern __shared__ char smem[];
    const uint32_t sb = smem_u32(smem);
    const int tid  = threadIdx.x;         // 256
    const int wid  = tid >> 5;
    const int lane = tid & 31;
    const int wm   = (wid & 1) * 64;      // warp row offset in tile
    const int wn   = (wid >> 1) * 32;     // warp col offset in tile
    const int m0 = blockIdx.y * 128;
    const int n0 = blockIdx.x * 128;

    const int KC = K >> 5;                // stages per pass
    const int S  = 3 * KC;                // total stages

    float acc[4][4][4];
    #pragma unroll
    for (int i = 0; i < 4; i++)
        #pragma unroll
        for (int j = 0; j < 4; j++)
            #pragma unroll
            for (int e = 0; e < 4; e++) acc[i][j][e] = 0.f;

    // stage loader
    auto load_stage = [&](int st) {
        const int pass = st / KC;
        const int k0 = (st - pass*KC) << 5;
        const __nv_bfloat16* Ap = (pass == 2) ? Alo : Ahi;
        const __nv_bfloat16* Bp = (pass == 1) ? Blo : Bhi;
        const uint32_t base = sb + (st % 3) * STAGE_BYTES;
        #pragma unroll
        for (int i = 0; i < 2; i++) {
            int c = tid + i*256;                   // [0,512)
            int row = c >> 2, g = c & 3;           // 4 x 16B chunks per row
            cp_async16(base + row*80 + g*16, Ap + (size_t)(m0 + row)*K + k0 + g*8);
            cp_async16(base + 128*80 + row*80 + g*16, Bp + (size_t)(n0 + row)*K + k0 + g*8);
        }
        CP_COMMIT();
    };

    load_stage(0);
    load_stage(1);

    // ldmatrix lane addressing (bytes)
    const int a_row = lane & 15;
    const int a_koff = (lane >> 4) * 16;           // 8 halves
    const int b_row = lane & 7;
    const int b_koff = ((lane >> 3) & 1) * 16;

    for (int st = 0; st < S; ++st) {
        if (st + 2 < S) load_stage(st + 2);
        CP_WAIT(2);
        __syncthreads();

        const uint32_t Asb = sb + (st % 3) * STAGE_BYTES;
        const uint32_t Bsb = Asb + 128*80;

        #pragma unroll
        for (int ks = 0; ks < 2; ++ks) {
            uint32_t a[4][4], b[4][2];
            #pragma unroll
            for (int mi = 0; mi < 4; ++mi)
                ldm_x4(a[mi][0], a[mi][1], a[mi][2], a[mi][3],
                       Asb + (wm + mi*16 + a_row)*80 + ks*32 + a_koff);
            #pragma unroll
            for (int ni = 0; ni < 4; ++ni)
                ldm_x2(b[ni][0], b[ni][1],
                       Bsb + (wn + ni*8 + b_row)*80 + ks*32 + b_koff);
            #pragma unroll
            for (int mi = 0; mi < 4; ++mi)
                #pragma unroll
                for (int ni = 0; ni < 4; ++ni)
                    mma_bf16(acc[mi][ni][0], acc[mi][ni][1], acc[mi][ni][2], acc[mi][ni][3],
                             a[mi][0], a[mi][1], a[mi][2], a[mi][3], b[ni][0], b[ni][1]);
        }
        __syncthreads();
    }

    // epilogue
    const int tg = lane >> 2;              // 0..7
    const int tc = (lane & 3) * 2;
    #pragma unroll
    for (int ni = 0; ni < 4; ++ni) {
        const int col = n0 + wn + ni*8 + tc;
        const float bz0 = bias[col], bz1 = bias[col + 1];
        #pragma unroll
        for (int mi = 0; mi < 4; ++mi) {
            const int row = m0 + wm + mi*16 + tg;
            float2 o0 = make_float2(acc[mi][ni][0] + bz0, acc[mi][ni][1] + bz1);
            float2 o1 = make_float2(acc[mi][ni][2] + bz0, acc[mi][ni][3] + bz1);
            if (RELU) {
                o0.x = fmaxf(o0.x, 0.f); o0.y = fmaxf(o0.y, 0.f);
                o1.x = fmaxf(o1.x, 0.f); o1.y = fmaxf(o1.y, 0.f);
            }
            *reinterpret_cast<float2*>(C + (size_t)row*N + col) = o0;
            *reinterpret_cast<float2*>(C + (size_t)(row + 8)*N + col) = o1;
        }
    }
}

template<bool RELU>
__global__ void __launch_bounds__(256) mma_gemm_kernel(
    const __nv_bfloat16* __restrict__ Ahi, const __nv_bfloat16* __restrict__ Alo,
    const __nv_bfloat16* __restrict__ Bhi, const __nv_bfloat16* __restrict__ Blo,
    const float* __restrict__ bias, float* __restrict__ C, int M, int N, int K)
{
    mma_gemm_body<RELU>(Ahi, Alo, Bhi, Blo, bias, C, M, N, K);
}

// QKV fused via blockIdx.z (weights laid out [4][512][512] per layer: q,k,v,o)
__global__ void __launch_bounds__(256) mma_gemm_qkv_kernel(
    const __nv_bfloat16* __restrict__ Ahi, const __nv_bfloat16* __restrict__ Alo,
    const __nv_bfloat16* __restrict__ Whi, const __nv_bfloat16* __restrict__ Wlo,
    const float* __restrict__ bq, const float* __restrict__ bk, const float* __restrict__ bv,
    float* __restrict__ q, float* __restrict__ k, float* __restrict__ v)
{
    const int z = blockIdx.z;
    const size_t woff = (size_t)z * DMODEL * DMODEL;
    const float* bias = (z == 0) ? bq : (z == 1) ? bk : bv;
    float* C = (z == 0) ? q : (z == 1) ? k : v;
    mma_gemm_body<false>(Ahi, Alo, Whi + woff, Wlo + woff, bias, C, NTOK, DMODEL, DMODEL);
}

// ---------------------------------------------------------------------------
// fp32 -> (hi,lo) bf16 split, elementwise (float4 granularity)
// ---------------------------------------------------------------------------
__global__ void aconv_kernel(const float* __restrict__ s, __nv_bfloat16* __restrict__ hi,
                             __nv_bfloat16* __restrict__ lo, int n4) {
    int i = blockIdx.x * blockDim.x + threadIdx.x;
    if (i >= n4) return;
    float4 x = reinterpret_cast<const float4*>(s)[i];
    __nv_bfloat16 h0 = __float2bfloat16(x.x), h1 = __float2bfloat16(x.y);
    __nv_bfloat16 h2 = __float2bfloat16(x.z), h3 = __float2bfloat16(x.w);
    ushort4 uh, ul;
    uh.x = __bfloat16_as_ushort(h0); uh.y = __bfloat16_as_ushort(h1);
    uh.z = __bfloat16_as_ushort(h2); uh.w = __bfloat16_as_ushort(h3);
    ul.x = __bfloat16_as_ushort(__float2bfloat16(x.x - __bfloat162float(h0)));
    ul.y = __bfloat16_as_ushort(__float2bfloat16(x.y - __bfloat162float(h1)));
    ul.z = __bfloat16_as_ushort(__float2bfloat16(x.z - __bfloat162float(h2)));
    ul.w = __bfloat16_as_ushort(__float2bfloat16(x.w - __bfloat162float(h3)));
    reinterpret_cast<ushort4*>(hi)[i] = uh;
    reinterpret_cast<ushort4*>(lo)[i] = ul;
}

// ---------------------------------------------------------------------------
// Weight transpose + split: W[K,N] fp32 -> Whi/Wlo[N,K] bf16. z = layer.
// ---------------------------------------------------------------------------
__global__ void wconv_t_kernel(const float* __restrict__ W, __nv_bfloat16* __restrict__ Whi,
                               __nv_bfloat16* __restrict__ Wlo, int K, int N,
                               size_t strideW, size_t strideO) {
    __shared__ float t[32][33];
    const int l = blockIdx.z;
    W += (size_t)l * strideW; Whi += (size_t)l * strideO; Wlo += (size_t)l * strideO;
    const int tx = threadIdx.x & 31, ty = threadIdx.x >> 5;   // 256 threads
    const int kb = blockIdx.y * 32, nb = blockIdx.x * 32;
    #pragma unroll
    for (int i = ty; i < 32; i += 8)
        t[i][tx] = W[(size_t)(kb + i)*N + nb + tx];
    __syncthreads();
    #pragma unroll
    for (int i = ty; i < 32; i += 8) {
        float x = t[tx][i];                       // = W[kb+tx][nb+i]
        __nv_bfloat16 h = __float2bfloat16(x);
        __nv_bfloat16 lo = __float2bfloat16(x - __bfloat162float(h));
        size_t o = (size_t)(nb + i)*K + kb + tx;  // out[n][k]
        Whi[o] = h; Wlo[o] = lo;
    }
}

// ---------------------------------------------------------------------------
// Embedding: h[t,d] = emb[x[t],d]*sqrt(D) + pos[t%SEQ, d]
// ---------------------------------------------------------------------------
__global__ void embed_kernel(const int* __restrict__ x, const float* __restrict__ emb,
                             const float* __restrict__ pos) {
    int idx = blockIdx.x * blockDim.x + threadIdx.x;
    int t = idx >> 9;
    int d = idx & 511;
    int s = t & (SEQ-1);
    int tok = x[t];
    g_h[idx] = emb[(size_t)tok*DMODEL + d] * SQRT_D + pos[(size_t)s*DMODEL + d];
}

// ---------------------------------------------------------------------------
// QE-skew precompute: SK[bh][i][j] = q_i . E[1023-i+j]  (only j in [0, i])
// ---------------------------------------------------------------------------
#define QESK_SMEM ((64*68 + 64*136) * sizeof(float))

__global__ void qe_skew_kernel(const float* __restrict__ q, const float* __restrict__ E,
                               float* __restrict__ SK) {
    extern __shared__ float sm[];
    float* qsT = sm;             // [d][i] stride 68
    float* esT = qsT + 64*68;    // [d][m_local] stride 136

    const int bh = blockIdx.y;
    const int b  = bh >> 3;
    const int h  = bh & 7;
    const int i0 = blockIdx.x * 64;
    const int tid = threadIdx.x;
    const int r = tid >> 4;
    const int c = tid & 15;
    const int tok0 = b * SEQ;
    const int hoff = h * DHEAD;

    #pragma unroll
    for (int t = 0; t < 4; t++) {
        int f = tid + t*256;
        int i = f >> 4, d4 = (f & 15) * 4;
        float4 qv = *reinterpret_cast<const float4*>(&q[(size_t)(tok0 + i0 + i)*DMODEL + hoff + d4]);
        qsT[(d4+0)*68 + i] = qv.x; qsT[(d4+1)*68 + i] = qv.y;
        qsT[(d4+2)*68 + i] = qv.z; qsT[(d4+3)*68 + i] = qv.w;
    }

    const int mt_lo = ((960 - i0) / 128) * 128;
    float* dst_base = SK + ((size_t)bh << 20);

    for (int mt = mt_lo; mt < 1024; mt += 128) {
        __syncthreads();
        #pragma unroll
        for (int t = 0; t < 8; t++) {
            int f = tid + t*256;
            int ml = f >> 4, d4 = (f & 15) * 4;
            float4 ev = *reinterpret_cast<const float4*>(&E[(size_t)(mt + ml)*DHEAD + d4]);
            esT[(d4+0)*136 + ml] = ev.x; esT[(d4+1)*136 + ml] = ev.y;
            esT[(d4+2)*136 + ml] = ev.z; esT[(d4+3)*136 + ml] = ev.w;
        }
        __syncthreads();

        float s[4][8];
        #pragma unroll
        for (int i = 0; i < 4; i++)
            #pragma unroll
            for (int j = 0; j < 8; j++) s[i][j] = 0.f;

        #pragma unroll 16
        for (int d = 0; d < 64; d++) {
            float4 a  = *reinterpret_cast<const float4*>(&qsT[d*68 + r*4]);
            float4 e0 = *reinterpret_cast<const float4*>(&esT[d*136 + c*8]);
            float4 e1 = *reinterpret_cast<const float4*>(&esT[d*136 + c*8 + 4]);
            float av[4] = {a.x, a.y, a.z, a.w};
            float ev[8] = {e0.x, e0.y, e0.z, e0.w, e1.x, e1.y, e1.z, e1.w};
            #pragma unroll
            for (int i = 0; i < 4; i++)
                #pragma unroll
                for (int j = 0; j < 8; j++)
                    s[i][j] = fmaf(av[i], ev[j], s[i][j]);
        }

        #pragma unroll
        for (int rr = 0; rr < 4; rr++) {
            int ig = i0 + r*4 + rr;
            int jb = mt + c*8 - 1023 + ig;
            float* dst = dst_base + ((size_t)ig << 10);
            #pragma unroll
            for (int cc = 0; cc < 8; cc++) {
                int j = jb + cc;
                if (j >= 0) dst[j] = s[rr][cc];
            }
        }
    }
}

// ---------------------------------------------------------------------------
// Flash attention with precomputed skewed rel term.
// ---------------------------------------------------------------------------
#define ATT_SMEM (4 * 64*68 * sizeof(float))

__global__ void attention_kernel(const float* __restrict__ q, const float* __restrict__ k,
                                 const float* __restrict__ v, const float* __restrict__ SK,
                                 float* __restrict__ out) {
    extern __shared__ float sm[];
    float* qsT = sm;
    float* ksT = qsT + 64*68;
    float* vs  = ksT + 64*68;
    float* psT = vs  + 64*68;

    const int bh = blockIdx.y;
    const int b  = bh >> 3;
    const int h  = bh & 7;
    const int i0 = blockIdx.x * 64;
    const int tid = threadIdx.x;
    const int r = tid >> 4;
    const int c = tid & 15;
    const int tok0 = b * SEQ;
    const int hoff = h * DHEAD;

    #pragma unroll
    for (int t = 0; t < 4; t++) {
        int f = tid + t*256;
        int i = f >> 4, d4 = (f & 15) * 4;
        float4 qv = *reinterpret_cast<const float4*>(&q[(size_t)(tok0 + i0 + i)*DMODEL + hoff + d4]);
        qsT[(d4+0)*68 + i] = qv.x; qsT[(d4+1)*68 + i] = qv.y;
        qsT[(d4+2)*68 + i] = qv.z; qsT[(d4+3)*68 + i] = qv.w;
    }

    float m_i[4], l_i[4], acc[4][4];
    #pragma unroll
    for (int i = 0; i < 4; i++) {
        m_i[i] = -1e30f; l_i[i] = 0.f;
        #pragma unroll
        for (int j = 0; j < 4; j++) acc[i][j] = 0.f;
    }

    const float* sk_base = SK + ((size_t)bh << 20);

    for (int jt = 0; jt < 16; jt++) {
        const int j0 = jt * 64;
        __syncthreads();
        #pragma unroll
        for (int t = 0; t < 4; t++) {
            int f = tid + t*256;
            int j = f >> 4, d4 = (f & 15) * 4;
            float4 kv = *reinterpret_cast<const float4*>(&k[(size_t)(tok0 + j0 + j)*DMODEL + hoff + d4]);
            ksT[(d4+0)*68 + j] = kv.x; ksT[(d4+1)*68 + j] = kv.y;
            ksT[(d4+2)*68 + j] = kv.z; ksT[(d4+3)*68 + j] = kv.w;
            float4 vv = *reinterpret_cast<const float4*>(&v[(size_t)(tok0 + j0 + j)*DMODEL + hoff + d4]);
            *reinterpret_cast<float4*>(&vs[j*68 + d4]) = vv;
        }
        __syncthreads();

        float s[4][4];
        #pragma unroll
        for (int i = 0; i < 4; i++)
            #pragma unroll
            for (int j = 0; j < 4; j++) s[i][j] = 0.f;

        #pragma unroll 16
        for (int d = 0; d < 64; d++) {
            float4 a  = *reinterpret_cast<const float4*>(&qsT[d*68 + r*4]);
            float4 bb = *reinterpret_cast<const float4*>(&ksT[d*68 + c*4]);
            float av[4] = {a.x, a.y, a.z, a.w};
            float bv[4] = {bb.x, bb.y, bb.z, bb.w};
            #pragma unroll
            for (int i = 0; i < 4; i++)
                #pragma unroll
                for (int j = 0; j < 4; j++)
                    s[i][j] = fmaf(av[i], bv[j], s[i][j]);
        }

        #pragma unroll
        for (int rr = 0; rr < 4; rr++) {
            int ig = i0 + r*4 + rr;
            int jb = j0 + c*4;
            const float* skp = sk_base + ((size_t)ig << 10) + jb;
            if (jb + 3 <= ig) {
                float4 sk4 = *reinterpret_cast<const float4*>(skp);
                s[rr][0] += sk4.x; s[rr][1] += sk4.y; s[rr][2] += sk4.z; s[rr][3] += sk4.w;
            } else if (jb <= ig) {
                #pragma unroll
                for (int cc = 0; cc < 4; cc++)
                    if (jb + cc <= ig) s[rr][cc] += skp[cc];
            }
        }

        #pragma unroll
        for (int rr = 0; rr < 4; rr++) {
            float mx = s[rr][0];
            #pragma unroll
            for (int cc = 1; cc < 4; cc++) mx = fmaxf(mx, s[rr][cc]);
            mx *= INV_SQRT_DH;
            mx = fmaxf(mx, __shfl_xor_sync(0xffffffffu, mx, 1));
            mx = fmaxf(mx, __shfl_xor_sync(0xffffffffu, mx, 2));
            mx = fmaxf(mx, __shfl_xor_sync(0xffffffffu, mx, 4));
            mx = fmaxf(mx, __shfl_xor_sync(0xffffffffu, mx, 8));
            float mn = fmaxf(m_i[rr], mx);
            float alpha = __expf(m_i[rr] - mn);
            float psum = 0.f;
            #pragma unroll
            for (int cc = 0; cc < 4; cc++) {
                float p = __expf(s[rr][cc] * INV_SQRT_DH - mn);
                psT[(c*4+cc)*68 + r*4 + rr] = p;
                psum += p;
            }
            psum += __shfl_xor_sync(0xffffffffu, psum, 1);
            psum += __shfl_xor_sync(0xffffffffu, psum, 2);
            psum += __shfl_xor_sync(0xffffffffu, psum, 4);
            psum += __shfl_xor_sync(0xffffffffu, psum, 8);
            l_i[rr] = l_i[rr] * alpha + psum;
            m_i[rr] = mn;
            #pragma unroll
            for (int cc = 0; cc < 4; cc++) acc[rr][cc] *= alpha;
        }
        __syncthreads();

        #pragma unroll 8
        for (int kk = 0; kk < 64; kk++) {
            float4 p  = *reinterpret_cast<const float4*>(&psT[kk*68 + r*4]);
            float4 vv = *reinterpret_cast<const float4*>(&vs[kk*68 + c*4]);
            float pv[4] = {p.x, p.y, p.z, p.w};
            float vvv[4] = {vv.x, vv.y, vv.z, vv.w};
            #pragma unroll
            for (int i = 0; i < 4; i++)
                #pragma unroll
                for (int j = 0; j < 4; j++)
                    acc[i][j] = fmaf(pv[i], vvv[j], acc[i][j]);
        }
    }

    #pragma unroll
    for (int rr = 0; rr < 4; rr++) {
        float inv = 1.f / l_i[rr];
        float4 o = make_float4(acc[rr][0]*inv, acc[rr][1]*inv, acc[rr][2]*inv, acc[rr][3]*inv);
        *reinterpret_cast<float4*>(&out[(size_t)(tok0 + i0 + r*4 + rr)*DMODEL + hoff + c*4]) = o;
    }
}

// ---------------------------------------------------------------------------
// y = LayerNorm(a + b) * scale + bias
// ---------------------------------------------------------------------------
__global__ void add_ln_kernel(const float* __restrict__ a, const float* __restrict__ b,
                              const float* __restrict__ scale, const float* __restrict__ bias,
                              float* __restrict__ y) {
    const int t = blockIdx.x;
    const int tid = threadIdx.x;
    float x[4];
    float sum = 0.f;
    #pragma unroll
    for (int i = 0; i < 4; i++) {
        int d = tid + i*128;
        x[i] = a[(size_t)t*DMODEL + d] + b[(size_t)t*DMODEL + d];
        sum += x[i];
    }
    __shared__ float red[4];
    #pragma unroll
    for (int o = 16; o > 0; o >>= 1) sum += __shfl_xor_sync(0xffffffffu, sum, o);
    if ((tid & 31) == 0) red[tid >> 5] = sum;
    __syncthreads();
    sum = red[0] + red[1] + red[2] + red[3];
    const float mu = sum * (1.f/512.f);
    float vs = 0.f;
    #pragma unroll
    for (int i = 0; i < 4; i++) { float dd = x[i] - mu; vs = fmaf(dd, dd, vs); }
    #pragma unroll
    for (int o = 16; o > 0; o >>= 1) vs += __shfl_xor_sync(0xffffffffu, vs, o);
    __shared__ float red2[4];
    if ((tid & 31) == 0) red2[tid >> 5] = vs;
    __syncthreads();
    vs = red2[0] + red2[1] + red2[2] + red2[3];
    const float rstd = rsqrtf(vs * (1.f/512.f) + 1e-6f);
    #pragma unroll
    for (int i = 0; i < 4; i++) {
        int d = tid + i*128;
        y[(size_t)t*DMODEL + d] = (x[i] - mu) * rstd * scale[d] + bias[d];
    }
}

// ---------------------------------------------------------------------------
// out[b,o] = tanh(h[b,0,:] . Wf[:,o] + bf[o])
// ---------------------------------------------------------------------------
__global__ void head_kernel(const float* __restrict__ Wf, const float* __restrict__ bf,
                            float* __restrict__ out) {
    const int w = threadIdx.x >> 5;
    const int lane = threadIdx.x & 31;
    const int b = w >> 1, o = w & 1;
    const float* hr = g_h + (size_t)b*SEQ*DMODEL;
    float sum = 0.f;
    #pragma unroll
    for (int d = lane; d < DMODEL; d += 32)
        sum = fmaf(hr[d], Wf[d*2 + o], sum);
    #pragma unroll
    for (int off = 16; off > 0; off >>= 1) sum += __shfl_xor_sync(0xffffffffu, sum, off);
    if (lane == 0) out[b*2 + o] = tanhf(sum + bf[o]);
}

// ---------------------------------------------------------------------------
// Launch
// ---------------------------------------------------------------------------
extern "C" void kernel_launch(void* const* d_in, const int* in_sizes, int n_in,
                              void* d_out, int out_size) {
    const int*   x    = (const int*)  d_in[0];
    const float* emb  = (const float*)d_in[1];
    const float* pos  = (const float*)d_in[2];
    const float* Wq   = (const float*)d_in[3];
    const float* bq   = (const float*)d_in[4];
    const float* Wk   = (const float*)d_in[5];
    const float* bk   = (const float*)d_in[6];
    const float* Wv   = (const float*)d_in[7];
    const float* bv   = (const float*)d_in[8];
    const float* Wo   = (const float*)d_in[9];
    const float* bo   = (const float*)d_in[10];
    const float* E    = (const float*)d_in[11];
    const float* W1   = (const float*)d_in[12];
    const float* b1   = (const float*)d_in[13];
    const float* W2   = (const float*)d_in[14];
    const float* b2   = (const float*)d_in[15];
    const float* ln1s = (const float*)d_in[16];
    const float* ln1b = (const float*)d_in[17];
    const float* ln2s = (const float*)d_in[18];
    const float* ln2b = (const float*)d_in[19];
    const float* Wf   = (const float*)d_in[20];
    const float* bf   = (const float*)d_in[21];
    float* out = (float*)d_out;

    float *h, *qb, *kb, *vb, *attn, *h1, *mid, *ffn, *sk;
    cudaGetSymbolAddress((void**)&h,    g_h);
    cudaGetSymbolAddress((void**)&qb,   g_q);
    cudaGetSymbolAddress((void**)&kb,   g_k);
    cudaGetSymbolAddress((void**)&vb,   g_v);
    cudaGetSymbolAddress((void**)&attn, g_attn);
    cudaGetSymbolAddress((void**)&h1,   g_h1);
    cudaGetSymbolAddress((void**)&mid,  g_mid);
    cudaGetSymbolAddress((void**)&ffn,  g_ffn);
    cudaGetSymbolAddress((void**)&sk,   g_sk);

    __nv_bfloat16 *ahi, *alo, *w4h, *w4l, *w1h, *w1l, *w2h, *w2l;
    cudaGetSymbolAddress((void**)&ahi, g_act_hi);
    cudaGetSymbolAddress((void**)&alo, g_act_lo);
    cudaGetSymbolAddress((void**)&w4h, g_w4_hi);
    cudaGetSymbolAddress((void**)&w4l, g_w4_lo);
    cudaGetSymbolAddress((void**)&w1h, g_w1_hi);
    cudaGetSymbolAddress((void**)&w1l, g_w1_lo);
    cudaGetSymbolAddress((void**)&w2h, g_w2_hi);
    cudaGetSymbolAddress((void**)&w2l, g_w2_lo);

    cudaFuncSetAttribute(attention_kernel, cudaFuncAttributeMaxDynamicSharedMemorySize, (int)ATT_SMEM);
    cudaFuncSetAttribute(qe_skew_kernel,   cudaFuncAttributeMaxDynamicSharedMemorySize, (int)QESK_SMEM);
    cudaFuncSetAttribute(mma_gemm_kernel<false>, cudaFuncAttributeMaxDynamicSharedMemorySize, MMA_SMEM);
    cudaFuncSetAttribute(mma_gemm_kernel<true>,  cudaFuncAttributeMaxDynamicSharedMemorySize, MMA_SMEM);
    cudaFuncSetAttribute(mma_gemm_qkv_kernel,    cudaFuncAttributeMaxDynamicSharedMemorySize, MMA_SMEM);

    const size_t SZ = (size_t)DMODEL * DMODEL;      // 262144

    // --- weight transpose + bf16 split (once per launch) ---
    wconv_t_kernel<<<dim3(16,16,NLAYER), 256>>>(Wq, w4h + 0*SZ, w4l + 0*SZ, DMODEL, DMODEL, SZ, 4*SZ);
    wconv_t_kernel<<<dim3(16,16,NLAYER), 256>>>(Wk, w4h + 1*SZ, w4l + 1*SZ, DMODEL, DMODEL, SZ, 4*SZ);
    wconv_t_kernel<<<dim3(16,16,NLAYER), 256>>>(Wv, w4h + 2*SZ, w4l + 2*SZ, DMODEL, DMODEL, SZ, 4*SZ);
    wconv_t_kernel<<<dim3(16,16,NLAYER), 256>>>(Wo, w4h + 3*SZ, w4l + 3*SZ, DMODEL, DMODEL, SZ, 4*SZ);
    wconv_t_kernel<<<dim3(64,16,NLAYER), 256>>>(W1, w1h, w1l, DMODEL, DINNER,
                                                (size_t)DMODEL*DINNER, (size_t)DINNER*DMODEL);
    wconv_t_kernel<<<dim3(16,64,NLAYER), 256>>>(W2, w2h, w2l, DINNER, DMODEL,
                                                (size_t)DINNER*DMODEL, (size_t)DMODEL*DINNER);

    embed_kernel<<<NTOK*DMODEL/256, 256>>>(x, emb, pos);

    for (int l = 0; l < NLAYER; l++) {
        const __nv_bfloat16* l4h = w4h + (size_t)l*4*SZ;
        const __nv_bfloat16* l4l = w4l + (size_t)l*4*SZ;

        aconv_kernel<<<NTOK*DMODEL/4/256, 256>>>(h, ahi, alo, NTOK*DMODEL/4);
        mma_gemm_qkv_kernel<<<dim3(4,32,3), 256, MMA_SMEM>>>(ahi, alo, l4h, l4l,
            bq + l*DMODEL, bk + l*DMODEL, bv + l*DMODEL, qb, kb, vb);

        qe_skew_kernel<<<dim3(16,32), 256, QESK_SMEM>>>(qb, E + (size_t)l*SEQ*DHEAD, sk);
        attention_kernel<<<dim3(16,32), 256, ATT_SMEM>>>(qb, kb, vb, sk, attn);

        aconv_kernel<<<NTOK*DMODEL/4/256, 256>>>(attn, ahi, alo, NTOK*DMODEL/4);
        mma_gemm_kernel<false><<<dim3(4,32), 256, MMA_SMEM>>>(ahi, alo, l4h + 3*SZ, l4l + 3*SZ,
            bo + l*DMODEL, ffn, NTOK, DMODEL, DMODEL);
        add_ln_kernel<<<NTOK, 128>>>(ffn, h, ln1s + l*DMODEL, ln1b + l*DMODEL, h1);

        aconv_kernel<<<NTOK*DMODEL/4/256, 256>>>(h1, ahi, alo, NTOK*DMODEL/4);
        mma_gemm_kernel<true><<<dim3(16,32), 256, MMA_SMEM>>>(ahi, alo,
            w1h + (size_t)l*DINNER*DMODEL, w1l + (size_t)l*DINNER*DMODEL,
            b1 + l*DINNER, mid, NTOK, DINNER, DMODEL);

        aconv_kernel<<<NTOK*DINNER/4/256, 256>>>(mid, ahi, alo, NTOK*DINNER/4);
        mma_gemm_kernel<false><<<dim3(4,32), 256, MMA_SMEM>>>(ahi, alo,
            w2h + (size_t)l*DMODEL*DINNER, w2l + (size_t)l*DMODEL*DINNER,
            b2 + l*DMODEL, ffn, NTOK, DMODEL, DINNER);
        add_ln_kernel<<<NTOK, 128>>>(h1, ffn, ln2s + l*DMODEL, ln2b + l*DMODEL, h);
    }

    head_kernel<<<1, 256>>>(Wf, bf, out);
}

// round 5
// speedup vs baseline: 3.0280x; 1.1676x over previous
#include <cuda_runtime.h>
#include <cuda_bf16.h>
#include <math.h>
#include <stdint.h>

// ---------------------------------------------------------------------------
// Problem constants
// ---------------------------------------------------------------------------
#define BATCH 4
#define SEQ   1024
#define DMODEL 512
#define DINNER 2048
#define NHEAD 8
#define DHEAD 64
#define NLAYER 6
#define NTOK (BATCH*SEQ)          // 4096
#define SQRT_D 22.627416997969522f
#define INV_SQRT_DH 0.125f

// ---------------------------------------------------------------------------
// Scratch (device globals: no allocations allowed)
// ---------------------------------------------------------------------------
__device__ float g_h   [NTOK*DMODEL];
__device__ float g_q   [NTOK*DMODEL];
__device__ float g_k   [NTOK*DMODEL];
__device__ float g_v   [NTOK*DMODEL];
__device__ float g_attn[NTOK*DMODEL];
__device__ float g_h1  [NTOK*DMODEL];
__device__ float g_ffn [NTOK*DMODEL];
__device__ float g_mid [NTOK*DINNER];
__device__ float g_sk  [32u*1024u*1024u];   // SK[bh][i][j] = q_i . E[1023-i+j], j<=i

// bf16 split operands
__device__ __nv_bfloat16 g_act_hi[NTOK*DINNER];
__device__ __nv_bfloat16 g_act_lo[NTOK*DINNER];
__device__ __nv_bfloat16 g_w4_hi[NLAYER*4*DMODEL*DMODEL];   // q,k,v,o transposed [N,K]
__device__ __nv_bfloat16 g_w4_lo[NLAYER*4*DMODEL*DMODEL];
__device__ __nv_bfloat16 g_w1_hi[NLAYER*DINNER*DMODEL];     // W1^T [2048,512]
__device__ __nv_bfloat16 g_w1_lo[NLAYER*DINNER*DMODEL];
__device__ __nv_bfloat16 g_w2_hi[NLAYER*DMODEL*DINNER];     // W2^T [512,2048]
__device__ __nv_bfloat16 g_w2_lo[NLAYER*DMODEL*DINNER];

// ---------------------------------------------------------------------------
// PTX helpers (base-target only: ldmatrix / mma.sync / cp.async)
// ---------------------------------------------------------------------------
__device__ __forceinline__ uint32_t smem_u32(const void* p) {
    uint32_t a;
    asm("{ .reg .u64 t; cvta.to.shared.u64 t, %1; cvt.u32.u64 %0, t; }" : "=r"(a) : "l"(p));
    return a;
}

__device__ __forceinline__ void cp_async16(uint32_t dst, const void* src) {
    asm volatile("cp.async.cg.shared.global [%0], [%1], 16;" :: "r"(dst), "l"(src));
}
#define CP_COMMIT() asm volatile("cp.async.commit_group;" ::: "memory")
#define CP_WAIT(N)  asm volatile("cp.async.wait_group %0;" :: "n"(N) : "memory")

__device__ __forceinline__ void ldm_x4(uint32_t& r0, uint32_t& r1, uint32_t& r2, uint32_t& r3,
                                       uint32_t addr) {
    asm volatile("ldmatrix.sync.aligned.m8n8.x4.shared.b16 {%0,%1,%2,%3}, [%4];"
                 : "=r"(r0), "=r"(r1), "=r"(r2), "=r"(r3) : "r"(addr));
}
__device__ __forceinline__ void ldm_x2(uint32_t& r0, uint32_t& r1, uint32_t addr) {
    asm volatile("ldmatrix.sync.aligned.m8n8.x2.shared.b16 {%0,%1}, [%2];"
                 : "=r"(r0), "=r"(r1) : "r"(addr));
}

__device__ __forceinline__ void mma_bf16(float& c0, float& c1, float& c2, float& c3,
                                         uint32_t a0, uint32_t a1, uint32_t a2, uint32_t a3,
                                         uint32_t b0, uint32_t b1) {
    asm volatile(
        "mma.sync.aligned.m16n8k16.row.col.f32.bf16.bf16.f32 "
        "{%0,%1,%2,%3}, {%4,%5,%6,%7}, {%8,%9}, {%0,%1,%2,%3};"
        : "+f"(c0), "+f"(c1), "+f"(c2), "+f"(c3)
        : "r"(a0), "r"(a1), "r"(a2), "r"(a3), "r"(b0), "r"(b1));
}

// fp32 pair -> packed bf16 hi pair + packed bf16 residual pair
__device__ __forceinline__ void split_pack(float x, float y, uint32_t& hi, uint32_t& lo) {
    __nv_bfloat16 bx = __float2bfloat16(x), by = __float2bfloat16(y);
    hi = (uint32_t)__bfloat16_as_ushort(bx) | ((uint32_t)__bfloat16_as_ushort(by) << 16);
    __nv_bfloat16 rx = __float2bfloat16(x - __bfloat162float(bx));
    __nv_bfloat16 ry = __float2bfloat16(y - __bfloat162float(by));
    lo = (uint32_t)__bfloat16_as_ushort(rx) | ((uint32_t)__bfloat16_as_ushort(ry) << 16);
}

// ---------------------------------------------------------------------------
// Tensor-core GEMM (mma.sync): C[M,N] = (Ahi+Alo)[M,K] @ (Bhi+Blo)^T[N,K] + bias
// bf16x3 split: hi*hi + hi*lo + lo*hi accumulated in fp32 fragments.
// CTA tile 128x128, 8 warps (2x4) of 64x32, BK=32, 3-stage cp.async pipeline.
// ---------------------------------------------------------------------------
#define STAGE_BYTES (2*128*80)          // A tile + B tile, one stage
#define MMA_SMEM    (3*STAGE_BYTES)     // 61440 B

template<bool RELU>
__device__ __forceinline__ void mma_gemm_body(
    const __nv_bfloat16* __restrict__ Ahi, const __nv_bfloat16* __restrict__ Alo,
    const __nv_bfloat16* __restrict__ Bhi, const __nv_bfloat16* __restrict__ Blo,
    const float* __restrict__ bias, float* __restrict__ C, int M, int N, int K)
{
    extern __shared__ char smem[];
    const uint32_t sb = smem_u32(smem);
    const int tid  = threadIdx.x;         // 256
    const int wid  = tid >> 5;
    const int lane = tid & 31;
    const int wm   = (wid & 1) * 64;
    const int wn   = (wid >> 1) * 32;
    const int m0 = blockIdx.y * 128;
    const int n0 = blockIdx.x * 128;

    const int KC = K >> 5;
    const int S  = 3 * KC;

    float acc[4][4][4];
    #pragma unroll
    for (int i = 0; i < 4; i++)
        #pragma unroll
        for (int j = 0; j < 4; j++)
            #pragma unroll
            for (int e = 0; e < 4; e++) acc[i][j][e] = 0.f;

    auto load_stage = [&](int st) {
        const int pass = st / KC;
        const int k0 = (st - pass*KC) << 5;
        const __nv_bfloat16* Ap = (pass == 2) ? Alo : Ahi;
        const __nv_bfloat16* Bp = (pass == 1) ? Blo : Bhi;
        const uint32_t base = sb + (st % 3) * STAGE_BYTES;
        #pragma unroll
        for (int i = 0; i < 2; i++) {
            int c = tid + i*256;
            int row = c >> 2, g = c & 3;
            cp_async16(base + row*80 + g*16, Ap + (size_t)(m0 + row)*K + k0 + g*8);
            cp_async16(base + 128*80 + row*80 + g*16, Bp + (size_t)(n0 + row)*K + k0 + g*8);
        }
        CP_COMMIT();
    };

    load_stage(0);
    load_stage(1);

    const int a_row = lane & 15;
    const int a_koff = (lane >> 4) * 16;
    const int b_row = lane & 7;
    const int b_koff = ((lane >> 3) & 1) * 16;

    for (int st = 0; st < S; ++st) {
        if (st + 2 < S) load_stage(st + 2);
        CP_WAIT(2);
        __syncthreads();

        const uint32_t Asb = sb + (st % 3) * STAGE_BYTES;
        const uint32_t Bsb = Asb + 128*80;

        #pragma unroll
        for (int ks = 0; ks < 2; ++ks) {
            uint32_t a[4][4], b[4][2];
            #pragma unroll
            for (int mi = 0; mi < 4; ++mi)
                ldm_x4(a[mi][0], a[mi][1], a[mi][2], a[mi][3],
                       Asb + (wm + mi*16 + a_row)*80 + ks*32 + a_koff);
            #pragma unroll
            for (int ni = 0; ni < 4; ++ni)
                ldm_x2(b[ni][0], b[ni][1],
                       Bsb + (wn + ni*8 + b_row)*80 + ks*32 + b_koff);
            #pragma unroll
            for (int mi = 0; mi < 4; ++mi)
                #pragma unroll
                for (int ni = 0; ni < 4; ++ni)
                    mma_bf16(acc[mi][ni][0], acc[mi][ni][1], acc[mi][ni][2], acc[mi][ni][3],
                             a[mi][0], a[mi][1], a[mi][2], a[mi][3], b[ni][0], b[ni][1]);
        }
        __syncthreads();
    }

    const int tg = lane >> 2;
    const int tc = (lane & 3) * 2;
    #pragma unroll
    for (int ni = 0; ni < 4; ++ni) {
        const int col = n0 + wn + ni*8 + tc;
        const float bz0 = bias[col], bz1 = bias[col + 1];
        #pragma unroll
        for (int mi = 0; mi < 4; ++mi) {
            const int row = m0 + wm + mi*16 + tg;
            float2 o0 = make_float2(acc[mi][ni][0] + bz0, acc[mi][ni][1] + bz1);
            float2 o1 = make_float2(acc[mi][ni][2] + bz0, acc[mi][ni][3] + bz1);
            if (RELU) {
                o0.x = fmaxf(o0.x, 0.f); o0.y = fmaxf(o0.y, 0.f);
                o1.x = fmaxf(o1.x, 0.f); o1.y = fmaxf(o1.y, 0.f);
            }
            *reinterpret_cast<float2*>(C + (size_t)row*N + col) = o0;
            *reinterpret_cast<float2*>(C + (size_t)(row + 8)*N + col) = o1;
        }
    }
}

template<bool RELU>
__global__ void __launch_bounds__(256) mma_gemm_kernel(
    const __nv_bfloat16* __restrict__ Ahi, const __nv_bfloat16* __restrict__ Alo,
    const __nv_bfloat16* __restrict__ Bhi, const __nv_bfloat16* __restrict__ Blo,
    const float* __restrict__ bias, float* __restrict__ C, int M, int N, int K)
{
    mma_gemm_body<RELU>(Ahi, Alo, Bhi, Blo, bias, C, M, N, K);
}

__global__ void __launch_bounds__(256) mma_gemm_qkv_kernel(
    const __nv_bfloat16* __restrict__ Ahi, const __nv_bfloat16* __restrict__ Alo,
    const __nv_bfloat16* __restrict__ Whi, const __nv_bfloat16* __restrict__ Wlo,
    const float* __restrict__ bq, const float* __restrict__ bk, const float* __restrict__ bv,
    float* __restrict__ q, float* __restrict__ k, float* __restrict__ v)
{
    const int z = blockIdx.z;
    const size_t woff = (size_t)z * DMODEL * DMODEL;
    const float* bias = (z == 0) ? bq : (z == 1) ? bk : bv;
    float* C = (z == 0) ? q : (z == 1) ? k : v;
    mma_gemm_body<false>(Ahi, Alo, Whi + woff, Wlo + woff, bias, C, NTOK, DMODEL, DMODEL);
}

// ---------------------------------------------------------------------------
// fp32 -> (hi,lo) bf16 split, elementwise (float4 granularity)
// ---------------------------------------------------------------------------
__global__ void aconv_kernel(const float* __restrict__ s, __nv_bfloat16* __restrict__ hi,
                             __nv_bfloat16* __restrict__ lo, int n4) {
    int i = blockIdx.x * blockDim.x + threadIdx.x;
    if (i >= n4) return;
    float4 x = reinterpret_cast<const float4*>(s)[i];
    uint32_t h0, l0, h1, l1;
    split_pack(x.x, x.y, h0, l0);
    split_pack(x.z, x.w, h1, l1);
    reinterpret_cast<uint2*>(hi)[i] = make_uint2(h0, h1);
    reinterpret_cast<uint2*>(lo)[i] = make_uint2(l0, l1);
}

// ---------------------------------------------------------------------------
// Weight transpose + split: W[K,N] fp32 -> Whi/Wlo[N,K] bf16. z = layer.
// ---------------------------------------------------------------------------
__global__ void wconv_t_kernel(const float* __restrict__ W, __nv_bfloat16* __restrict__ Whi,
                               __nv_bfloat16* __restrict__ Wlo, int K, int N,
                               size_t strideW, size_t strideO) {
    __shared__ float t[32][33];
    const int l = blockIdx.z;
    W += (size_t)l * strideW; Whi += (size_t)l * strideO; Wlo += (size_t)l * strideO;
    const int tx = threadIdx.x & 31, ty = threadIdx.x >> 5;
    const int kb = blockIdx.y * 32, nb = blockIdx.x * 32;
    #pragma unroll
    for (int i = ty; i < 32; i += 8)
        t[i][tx] = W[(size_t)(kb + i)*N + nb + tx];
    __syncthreads();
    #pragma unroll
    for (int i = ty; i < 32; i += 8) {
        float x = t[tx][i];
        __nv_bfloat16 h = __float2bfloat16(x);
        __nv_bfloat16 lo = __float2bfloat16(x - __bfloat162float(h));
        size_t o = (size_t)(nb + i)*K + kb + tx;
        Whi[o] = h; Wlo[o] = lo;
    }
}

// ---------------------------------------------------------------------------
// Embedding: h[t,d] = emb[x[t],d]*sqrt(D) + pos[t%SEQ, d]
// ---------------------------------------------------------------------------
__global__ void embed_kernel(const int* __restrict__ x, const float* __restrict__ emb,
                             const float* __restrict__ pos) {
    int idx = blockIdx.x * blockDim.x + threadIdx.x;
    int t = idx >> 9;
    int d = idx & 511;
    int s = t & (SEQ-1);
    int tok = x[t];
    g_h[idx] = emb[(size_t)tok*DMODEL + d] * SQRT_D + pos[(size_t)s*DMODEL + d];
}

// ---------------------------------------------------------------------------
// QE-skew precompute: SK[bh][i][j] = q_i . E[1023-i+j]  (only j in [0, i])
// ---------------------------------------------------------------------------
#define QESK_SMEM ((64*68 + 64*136) * sizeof(float))

__global__ void qe_skew_kernel(const float* __restrict__ q, const float* __restrict__ E,
                               float* __restrict__ SK) {
    extern __shared__ float sm[];
    float* qsT = sm;             // [d][i] stride 68
    float* esT = qsT + 64*68;    // [d][m_local] stride 136

    const int bh = blockIdx.y;
    const int b  = bh >> 3;
    const int h  = bh & 7;
    const int i0 = blockIdx.x * 64;
    const int tid = threadIdx.x;
    const int r = tid >> 4;
    const int c = tid & 15;
    const int tok0 = b * SEQ;
    const int hoff = h * DHEAD;

    #pragma unroll
    for (int t = 0; t < 4; t++) {
        int f = tid + t*256;
        int i = f >> 4, d4 = (f & 15) * 4;
        float4 qv = *reinterpret_cast<const float4*>(&q[(size_t)(tok0 + i0 + i)*DMODEL + hoff + d4]);
        qsT[(d4+0)*68 + i] = qv.x; qsT[(d4+1)*68 + i] = qv.y;
        qsT[(d4+2)*68 + i] = qv.z; qsT[(d4+3)*68 + i] = qv.w;
    }

    const int mt_lo = ((960 - i0) / 128) * 128;
    float* dst_base = SK + ((size_t)bh << 20);

    for (int mt = mt_lo; mt < 1024; mt += 128) {
        __syncthreads();
        #pragma unroll
        for (int t = 0; t < 8; t++) {
            int f = tid + t*256;
            int ml = f >> 4, d4 = (f & 15) * 4;
            float4 ev = *reinterpret_cast<const float4*>(&E[(size_t)(mt + ml)*DHEAD + d4]);
            esT[(d4+0)*136 + ml] = ev.x; esT[(d4+1)*136 + ml] = ev.y;
            esT[(d4+2)*136 + ml] = ev.z; esT[(d4+3)*136 + ml] = ev.w;
        }
        __syncthreads();

        float s[4][8];
        #pragma unroll
        for (int i = 0; i < 4; i++)
            #pragma unroll
            for (int j = 0; j < 8; j++) s[i][j] = 0.f;

        #pragma unroll 16
        for (int d = 0; d < 64; d++) {
            float4 a  = *reinterpret_cast<const float4*>(&qsT[d*68 + r*4]);
            float4 e0 = *reinterpret_cast<const float4*>(&esT[d*136 + c*8]);
            float4 e1 = *reinterpret_cast<const float4*>(&esT[d*136 + c*8 + 4]);
            float av[4] = {a.x, a.y, a.z, a.w};
            float ev[8] = {e0.x, e0.y, e0.z, e0.w, e1.x, e1.y, e1.z, e1.w};
            #pragma unroll
            for (int i = 0; i < 4; i++)
                #pragma unroll
                for (int j = 0; j < 8; j++)
                    s[i][j] = fmaf(av[i], ev[j], s[i][j]);
        }

        #pragma unroll
        for (int rr = 0; rr < 4; rr++) {
            int ig = i0 + r*4 + rr;
            int jb = mt + c*8 - 1023 + ig;
            float* dst = dst_base + ((size_t)ig << 10);
            #pragma unroll
            for (int cc = 0; cc < 8; cc++) {
                int j = jb + cc;
                if (j >= 0) dst[j] = s[rr][cc];
            }
        }
    }
}

// ---------------------------------------------------------------------------
// Flash attention on tensor cores (mma.sync, bf16x3 split).
// One block = (bh, 64 query rows); 4 warps x 16 rows. 16 key tiles of 64.
// smem: q_hi/q_lo [64x72], k_hi/k_lo [64x72], vT_hi/vT_lo [64(d)x72] bf16
// ---------------------------------------------------------------------------
#define AT2_SMEM (6 * 64*72 * 2)   // 55296 B

__global__ void __launch_bounds__(128) attention2_kernel(
    const float* __restrict__ q, const float* __restrict__ k,
    const float* __restrict__ v, const float* __restrict__ SK,
    float* __restrict__ out)
{
    extern __shared__ char smembuf[];
    const uint32_t sb = smem_u32(smembuf);
    __nv_bfloat16* smh = reinterpret_cast<__nv_bfloat16*>(smembuf);
    // half-element offsets
    const int QHI = 0, QLO = 4608, KHI = 9216, KLO = 13824, VTH = 18432, VTL = 23040;

    const int bh = blockIdx.y;
    const int b  = bh >> 3;
    const int h  = bh & 7;
    const int i0 = blockIdx.x * 64;
    const int tid  = threadIdx.x;      // 128
    const int wid  = tid >> 5;
    const int lane = tid & 31;
    const int tok0 = b * SEQ;
    const int hoff = h * DHEAD;
    const int wq = wid * 16;

    // load + split Q tile (64x64)
    #pragma unroll
    for (int t = 0; t < 8; t++) {
        int f = tid + t*128;
        int r = f >> 4, d4 = (f & 15) * 4;
        float4 qv = *reinterpret_cast<const float4*>(&q[(size_t)(tok0 + i0 + r)*DMODEL + hoff + d4]);
        uint32_t h0, l0, h1, l1;
        split_pack(qv.x, qv.y, h0, l0);
        split_pack(qv.z, qv.w, h1, l1);
        int off = r*72 + d4;
        *reinterpret_cast<uint2*>(smh + QHI + off) = make_uint2(h0, h1);
        *reinterpret_cast<uint2*>(smh + QLO + off) = make_uint2(l0, l1);
    }

    float m_i[2] = {-1e30f, -1e30f}, l_i[2] = {0.f, 0.f};
    float acc[8][4];
    #pragma unroll
    for (int n = 0; n < 8; n++)
        #pragma unroll
        for (int e = 0; e < 4; e++) acc[n][e] = 0.f;

    const float* skb = SK + ((size_t)bh << 20);
    const int row0 = i0 + wq + (lane >> 2);   // global query row (frag upper row)
    const int qc = (lane & 3) * 2;            // frag col offset within 8

    // ldmatrix lane addressing
    const uint32_t a_addr0 = sb + ((uint32_t)((wq + (lane & 15))*72 + (lane >> 4)*8)) * 2;
    const uint32_t b_roff  = ((uint32_t)((lane & 7)*72 + ((lane >> 3) & 1)*8)) * 2;

    for (int jt = 0; jt < 16; jt++) {
        const int j0 = jt * 64;
        __syncthreads();
        // load + split K (row-major) and V (transposed) tiles
        #pragma unroll
        for (int t = 0; t < 8; t++) {
            int f = tid + t*128;
            int r = f >> 4, d4 = (f & 15) * 4;
            float4 kv = *reinterpret_cast<const float4*>(&k[(size_t)(tok0 + j0 + r)*DMODEL + hoff + d4]);
            uint32_t h0, l0, h1, l1;
            split_pack(kv.x, kv.y, h0, l0);
            split_pack(kv.z, kv.w, h1, l1);
            int off = r*72 + d4;
            *reinterpret_cast<uint2*>(smh + KHI + off) = make_uint2(h0, h1);
            *reinterpret_cast<uint2*>(smh + KLO + off) = make_uint2(l0, l1);

            float4 vv = *reinterpret_cast<const float4*>(&v[(size_t)(tok0 + j0 + r)*DMODEL + hoff + d4]);
            float ve[4] = {vv.x, vv.y, vv.z, vv.w};
            #pragma unroll
            for (int e = 0; e < 4; e++) {
                __nv_bfloat16 bh16 = __float2bfloat16(ve[e]);
                __nv_bfloat16 bl16 = __float2bfloat16(ve[e] - __bfloat162float(bh16));
                smh[VTH + (d4+e)*72 + r] = bh16;
                smh[VTL + (d4+e)*72 + r] = bl16;
            }
        }
        __syncthreads();

        // ---- S = Q K^T (bf16x3) ----
        float s[8][4];
        #pragma unroll
        for (int n = 0; n < 8; n++)
            #pragma unroll
            for (int e = 0; e < 4; e++) s[n][e] = 0.f;

        #pragma unroll
        for (int kt = 0; kt < 4; kt++) {
            uint32_t ah[4], al[4];
            ldm_x4(ah[0], ah[1], ah[2], ah[3], a_addr0 + kt*32);
            ldm_x4(al[0], al[1], al[2], al[3], a_addr0 + QLO*2 + kt*32);
            #pragma unroll
            for (int n = 0; n < 8; n++) {
                uint32_t ba = sb + KHI*2 + (uint32_t)(8*n*72)*2 + b_roff + kt*32;
                uint32_t bh0, bh1, bl0, bl1;
                ldm_x2(bh0, bh1, ba);
                ldm_x2(bl0, bl1, ba + (KLO - KHI)*2);
                mma_bf16(s[n][0], s[n][1], s[n][2], s[n][3], ah[0], ah[1], ah[2], ah[3], bh0, bh1);
                mma_bf16(s[n][0], s[n][1], s[n][2], s[n][3], ah[0], ah[1], ah[2], ah[3], bl0, bl1);
                mma_bf16(s[n][0], s[n][1], s[n][2], s[n][3], al[0], al[1], al[2], al[3], bh0, bh1);
            }
        }

        // ---- add rel-position term (j<=i), scale ----
        #pragma unroll
        for (int n = 0; n < 8; n++) {
            int jc = j0 + 8*n + qc;
            const float* p0 = skb + ((size_t)row0 << 10) + jc;
            const float* p1 = p0 + (8 << 10);
            if (jc     <= row0)     s[n][0] += p0[0];
            if (jc + 1 <= row0)     s[n][1] += p0[1];
            if (jc     <= row0 + 8) s[n][2] += p1[0];
            if (jc + 1 <= row0 + 8) s[n][3] += p1[1];
            #pragma unroll
            for (int e = 0; e < 4; e++) s[n][e] *= INV_SQRT_DH;
        }

        // ---- online softmax (rows r, r+8 per thread) ----
        #pragma unroll
        for (int rr = 0; rr < 2; rr++) {
            float mx = -1e30f;
            #pragma unroll
            for (int n = 0; n < 8; n++) {
                mx = fmaxf(mx, s[n][2*rr]);
                mx = fmaxf(mx, s[n][2*rr + 1]);
            }
            mx = fmaxf(mx, __shfl_xor_sync(0xffffffffu, mx, 1));
            mx = fmaxf(mx, __shfl_xor_sync(0xffffffffu, mx, 2));
            float mn = fmaxf(m_i[rr], mx);
            float alpha = __expf(m_i[rr] - mn);
            float ps = 0.f;
            #pragma unroll
            for (int n = 0; n < 8; n++) {
                float p0 = __expf(s[n][2*rr]     - mn);
                float p1 = __expf(s[n][2*rr + 1] - mn);
                s[n][2*rr] = p0; s[n][2*rr + 1] = p1;
                ps += p0 + p1;
            }
            ps += __shfl_xor_sync(0xffffffffu, ps, 1);
            ps += __shfl_xor_sync(0xffffffffu, ps, 2);
            l_i[rr] = l_i[rr] * alpha + ps;
            m_i[rr] = mn;
            #pragma unroll
            for (int dn = 0; dn < 8; dn++) {
                acc[dn][2*rr]     *= alpha;
                acc[dn][2*rr + 1] *= alpha;
            }
        }

        // ---- pack P into bf16 hi/lo A-fragments ----
        uint32_t ph[8][2], pl[8][2];
        #pragma unroll
        for (int n = 0; n < 8; n++) {
            split_pack(s[n][0], s[n][1], ph[n][0], pl[n][0]);
            split_pack(s[n][2], s[n][3], ph[n][1], pl[n][1]);
        }

        // ---- O += P V (bf16x3) ----
        #pragma unroll
        for (int kt = 0; kt < 4; kt++) {
            uint32_t ah0 = ph[2*kt][0], ah1 = ph[2*kt][1], ah2 = ph[2*kt+1][0], ah3 = ph[2*kt+1][1];
            uint32_t al0 = pl[2*kt][0], al1 = pl[2*kt][1], al2 = pl[2*kt+1][0], al3 = pl[2*kt+1][1];
            #pragma unroll
            for (int dn = 0; dn < 8; dn++) {
                uint32_t ba = sb + VTH*2 + (uint32_t)(8*dn*72)*2 + b_roff + kt*32;
                uint32_t bh0, bh1, bl0, bl1;
                ldm_x2(bh0, bh1, ba);
                ldm_x2(bl0, bl1, ba + (VTL - VTH)*2);
                mma_bf16(acc[dn][0], acc[dn][1], acc[dn][2], acc[dn][3], ah0, ah1, ah2, ah3, bh0, bh1);
                mma_bf16(acc[dn][0], acc[dn][1], acc[dn][2], acc[dn][3], al0, al1, al2, al3, bh0, bh1);
                mma_bf16(acc[dn][0], acc[dn][1], acc[dn][2], acc[dn][3], ah0, ah1, ah2, ah3, bl0, bl1);
            }
        }
    }

    // ---- normalize + store ----
    #pragma unroll
    for (int rr = 0; rr < 2; rr++) {
        float inv = 1.f / l_i[rr];
        int row = row0 + rr*8;
        #pragma unroll
        for (int dn = 0; dn < 8; dn++) {
            float2 o = make_float2(acc[dn][2*rr] * inv, acc[dn][2*rr + 1] * inv);
            *reinterpret_cast<float2*>(&out[(size_t)(tok0 + row)*DMODEL + hoff + 8*dn + qc]) = o;
        }
    }
}

// ---------------------------------------------------------------------------
// y = LayerNorm(a + b) * scale + bias
// ---------------------------------------------------------------------------
__global__ void add_ln_kernel(const float* __restrict__ a, const float* __restrict__ b,
                              const float* __restrict__ scale, const float* __restrict__ bias,
                              float* __restrict__ y) {
    const int t = blockIdx.x;
    const int tid = threadIdx.x;
    float x[4];
    float sum = 0.f;
    #pragma unroll
    for (int i = 0; i < 4; i++) {
        int d = tid + i*128;
        x[i] = a[(size_t)t*DMODEL + d] + b[(size_t)t*DMODEL + d];
        sum += x[i];
    }
    __shared__ float red[4];
    #pragma unroll
    for (int o = 16; o > 0; o >>= 1) sum += __shfl_xor_sync(0xffffffffu, sum, o);
    if ((tid & 31) == 0) red[tid >> 5] = sum;
    __syncthreads();
    sum = red[0] + red[1] + red[2] + red[3];
    const float mu = sum * (1.f/512.f);
    float vs = 0.f;
    #pragma unroll
    for (int i = 0; i < 4; i++) { float dd = x[i] - mu; vs = fmaf(dd, dd, vs); }
    #pragma unroll
    for (int o = 16; o > 0; o >>= 1) vs += __shfl_xor_sync(0xffffffffu, vs, o);
    __shared__ float red2[4];
    if ((tid & 31) == 0) red2[tid >> 5] = vs;
    __syncthreads();
    vs = red2[0] + red2[1] + red2[2] + red2[3];
    const float rstd = rsqrtf(vs * (1.f/512.f) + 1e-6f);
    #pragma unroll
    for (int i = 0; i < 4; i++) {
        int d = tid + i*128;
        y[(size_t)t*DMODEL + d] = (x[i] - mu) * rstd * scale[d] + bias[d];
    }
}

// ---------------------------------------------------------------------------
// out[b,o] = tanh(h[b,0,:] . Wf[:,o] + bf[o])
// ---------------------------------------------------------------------------
__global__ void head_kernel(const float* __restrict__ Wf, const float* __restrict__ bf,
                            float* __restrict__ out) {
    const int w = threadIdx.x >> 5;
    const int lane = threadIdx.x & 31;
    const int b = w >> 1, o = w & 1;
    const float* hr = g_h + (size_t)b*SEQ*DMODEL;
    float sum = 0.f;
    #pragma unroll
    for (int d = lane; d < DMODEL; d += 32)
        sum = fmaf(hr[d], Wf[d*2 + o], sum);
    #pragma unroll
    for (int off = 16; off > 0; off >>= 1) sum += __shfl_xor_sync(0xffffffffu, sum, off);
    if (lane == 0) out[b*2 + o] = tanhf(sum + bf[o]);
}

// ---------------------------------------------------------------------------
// Launch
// ---------------------------------------------------------------------------
extern "C" void kernel_launch(void* const* d_in, const int* in_sizes, int n_in,
                              void* d_out, int out_size) {
    const int*   x    = (const int*)  d_in[0];
    const float* emb  = (const float*)d_in[1];
    const float* pos  = (const float*)d_in[2];
    const float* Wq   = (const float*)d_in[3];
    const float* bq   = (const float*)d_in[4];
    const float* Wk   = (const float*)d_in[5];
    const float* bk   = (const float*)d_in[6];
    const float* Wv   = (const float*)d_in[7];
    const float* bv   = (const float*)d_in[8];
    const float* Wo   = (const float*)d_in[9];
    const float* bo   = (const float*)d_in[10];
    const float* E    = (const float*)d_in[11];
    const float* W1   = (const float*)d_in[12];
    const float* b1   = (const float*)d_in[13];
    const float* W2   = (const float*)d_in[14];
    const float* b2   = (const float*)d_in[15];
    const float* ln1s = (const float*)d_in[16];
    const float* ln1b = (const float*)d_in[17];
    const float* ln2s = (const float*)d_in[18];
    const float* ln2b = (const float*)d_in[19];
    const float* Wf   = (const float*)d_in[20];
    const float* bf   = (const float*)d_in[21];
    float* out = (float*)d_out;

    float *h, *qb, *kb, *vb, *attn, *h1, *mid, *ffn, *sk;
    cudaGetSymbolAddress((void**)&h,    g_h);
    cudaGetSymbolAddress((void**)&qb,   g_q);
    cudaGetSymbolAddress((void**)&kb,   g_k);
    cudaGetSymbolAddress((void**)&vb,   g_v);
    cudaGetSymbolAddress((void**)&attn, g_attn);
    cudaGetSymbolAddress((void**)&h1,   g_h1);
    cudaGetSymbolAddress((void**)&mid,  g_mid);
    cudaGetSymbolAddress((void**)&ffn,  g_ffn);
    cudaGetSymbolAddress((void**)&sk,   g_sk);

    __nv_bfloat16 *ahi, *alo, *w4h, *w4l, *w1h, *w1l, *w2h, *w2l;
    cudaGetSymbolAddress((void**)&ahi, g_act_hi);
    cudaGetSymbolAddress((void**)&alo, g_act_lo);
    cudaGetSymbolAddress((void**)&w4h, g_w4_hi);
    cudaGetSymbolAddress((void**)&w4l, g_w4_lo);
    cudaGetSymbolAddress((void**)&w1h, g_w1_hi);
    cudaGetSymbolAddress((void**)&w1l, g_w1_lo);
    cudaGetSymbolAddress((void**)&w2h, g_w2_hi);
    cudaGetSymbolAddress((void**)&w2l, g_w2_lo);

    cudaFuncSetAttribute(attention2_kernel, cudaFuncAttributeMaxDynamicSharedMemorySize, AT2_SMEM);
    cudaFuncSetAttribute(qe_skew_kernel,    cudaFuncAttributeMaxDynamicSharedMemorySize, (int)QESK_SMEM);
    cudaFuncSetAttribute(mma_gemm_kernel<false>, cudaFuncAttributeMaxDynamicSharedMemorySize, MMA_SMEM);
    cudaFuncSetAttribute(mma_gemm_kernel<true>,  cudaFuncAttributeMaxDynamicSharedMemorySize, MMA_SMEM);
    cudaFuncSetAttribute(mma_gemm_qkv_kernel,    cudaFuncAttributeMaxDynamicSharedMemorySize, MMA_SMEM);

    const size_t SZ = (size_t)DMODEL * DMODEL;      // 262144

    // --- weight transpose + bf16 split (once per launch) ---
    wconv_t_kernel<<<dim3(16,16,NLAYER), 256>>>(Wq, w4h + 0*SZ, w4l + 0*SZ, DMODEL, DMODEL, SZ, 4*SZ);
    wconv_t_kernel<<<dim3(16,16,NLAYER), 256>>>(Wk, w4h + 1*SZ, w4l + 1*SZ, DMODEL, DMODEL, SZ, 4*SZ);
    wconv_t_kernel<<<dim3(16,16,NLAYER), 256>>>(Wv, w4h + 2*SZ, w4l + 2*SZ, DMODEL, DMODEL, SZ, 4*SZ);
    wconv_t_kernel<<<dim3(16,16,NLAYER), 256>>>(Wo, w4h + 3*SZ, w4l + 3*SZ, DMODEL, DMODEL, SZ, 4*SZ);
    wconv_t_kernel<<<dim3(64,16,NLAYER), 256>>>(W1, w1h, w1l, DMODEL, DINNER,
                                                (size_t)DMODEL*DINNER, (size_t)DINNER*DMODEL);
    wconv_t_kernel<<<dim3(16,64,NLAYER), 256>>>(W2, w2h, w2l, DINNER, DMODEL,
                                                (size_t)DINNER*DMODEL, (size_t)DMODEL*DINNER);

    embed_kernel<<<NTOK*DMODEL/256, 256>>>(x, emb, pos);

    for (int l = 0; l < NLAYER; l++) {
        const __nv_bfloat16* l4h = w4h + (size_t)l*4*SZ;
        const __nv_bfloat16* l4l = w4l + (size_t)l*4*SZ;

        aconv_kernel<<<NTOK*DMODEL/4/256, 256>>>(h, ahi, alo, NTOK*DMODEL/4);
        mma_gemm_qkv_kernel<<<dim3(4,32,3), 256, MMA_SMEM>>>(ahi, alo, l4h, l4l,
            bq + l*DMODEL, bk + l*DMODEL, bv + l*DMODEL, qb, kb, vb);

        qe_skew_kernel<<<dim3(16,32), 256, QESK_SMEM>>>(qb, E + (size_t)l*SEQ*DHEAD, sk);
        attention2_kernel<<<dim3(16,32), 128, AT2_SMEM>>>(qb, kb, vb, sk, attn);

        aconv_kernel<<<NTOK*DMODEL/4/256, 256>>>(attn, ahi, alo, NTOK*DMODEL/4);
        mma_gemm_kernel<false><<<dim3(4,32), 256, MMA_SMEM>>>(ahi, alo, l4h + 3*SZ, l4l + 3*SZ,
            bo + l*DMODEL, ffn, NTOK, DMODEL, DMODEL);
        add_ln_kernel<<<NTOK, 128>>>(ffn, h, ln1s + l*DMODEL, ln1b + l*DMODEL, h1);

        aconv_kernel<<<NTOK*DMODEL/4/256, 256>>>(h1, ahi, alo, NTOK*DMODEL/4);
        mma_gemm_kernel<true><<<dim3(16,32), 256, MMA_SMEM>>>(ahi, alo,
            w1h + (size_t)l*DINNER*DMODEL, w1l + (size_t)l*DINNER*DMODEL,
            b1 + l*DINNER, mid, NTOK, DINNER, DMODEL);

        aconv_kernel<<<NTOK*DINNER/4/256, 256>>>(mid, ahi, alo, NTOK*DINNER/4);
        mma_gemm_kernel<false><<<dim3(4,32), 256, MMA_SMEM>>>(ahi, alo,
            w2h + (size_t)l*DMODEL*DINNER, w2l + (size_t)l*DMODEL*DINNER,
            b2 + l*DMODEL, ffn, NTOK, DMODEL, DINNER);
        add_ln_kernel<<<NTOK, 128>>>(h1, ffn, ln2s + l*DMODEL, ln2b + l*DMODEL, h);
    }

    head_kernel<<<1, 256>>>(Wf, bf, out);
}

// round 6
// speedup vs baseline: 4.0130x; 1.3253x over previous
#include <cuda_runtime.h>
#include <cuda_bf16.h>
#include <math.h>
#include <stdint.h>

// ---------------------------------------------------------------------------
// Problem constants
// ---------------------------------------------------------------------------
#define BATCH 4
#define SEQ   1024
#define DMODEL 512
#define DINNER 2048
#define NHEAD 8
#define DHEAD 64
#define NLAYER 6
#define NTOK (BATCH*SEQ)          // 4096
#define SQRT_D 22.627416997969522f
#define INV_SQRT_DH 0.125f

// ---------------------------------------------------------------------------
// Scratch (device globals: no allocations allowed)
// ---------------------------------------------------------------------------
__device__ float g_h   [NTOK*DMODEL];
__device__ float g_q   [NTOK*DMODEL];
__device__ float g_k   [NTOK*DMODEL];
__device__ float g_v   [NTOK*DMODEL];
__device__ float g_h1  [NTOK*DMODEL];
__device__ float g_ffn [NTOK*DMODEL];
__device__ float g_sk  [32u*1024u*1024u];   // SK[bh][i][j] = q_i . E[1023-i+j], j<=i

// bf16 split operand buffers (per-producer)
__device__ __nv_bfloat16 g_h_hi   [NTOK*DMODEL];
__device__ __nv_bfloat16 g_h_lo   [NTOK*DMODEL];
__device__ __nv_bfloat16 g_attn_hi[NTOK*DMODEL];
__device__ __nv_bfloat16 g_attn_lo[NTOK*DMODEL];
__device__ __nv_bfloat16 g_h1_hi  [NTOK*DMODEL];
__device__ __nv_bfloat16 g_h1_lo  [NTOK*DMODEL];
__device__ __nv_bfloat16 g_mid_hi [NTOK*DINNER];
__device__ __nv_bfloat16 g_mid_lo [NTOK*DINNER];

__device__ __nv_bfloat16 g_w4_hi[NLAYER*4*DMODEL*DMODEL];   // q,k,v,o transposed [N,K]
__device__ __nv_bfloat16 g_w4_lo[NLAYER*4*DMODEL*DMODEL];
__device__ __nv_bfloat16 g_w1_hi[NLAYER*DINNER*DMODEL];     // W1^T
__device__ __nv_bfloat16 g_w1_lo[NLAYER*DINNER*DMODEL];
__device__ __nv_bfloat16 g_w2_hi[NLAYER*DMODEL*DINNER];     // W2^T
__device__ __nv_bfloat16 g_w2_lo[NLAYER*DMODEL*DINNER];

// ---------------------------------------------------------------------------
// PTX helpers (base-target only: ldmatrix / mma.sync / cp.async)
// ---------------------------------------------------------------------------
__device__ __forceinline__ uint32_t smem_u32(const void* p) {
    uint32_t a;
    asm("{ .reg .u64 t; cvta.to.shared.u64 t, %1; cvt.u32.u64 %0, t; }" : "=r"(a) : "l"(p));
    return a;
}

__device__ __forceinline__ void cp_async16(uint32_t dst, const void* src) {
    asm volatile("cp.async.cg.shared.global [%0], [%1], 16;" :: "r"(dst), "l"(src));
}
#define CP_COMMIT() asm volatile("cp.async.commit_group;" ::: "memory")
#define CP_WAIT(N)  asm volatile("cp.async.wait_group %0;" :: "n"(N) : "memory")

__device__ __forceinline__ void ldm_x4(uint32_t& r0, uint32_t& r1, uint32_t& r2, uint32_t& r3,
                                       uint32_t addr) {
    asm volatile("ldmatrix.sync.aligned.m8n8.x4.shared.b16 {%0,%1,%2,%3}, [%4];"
                 : "=r"(r0), "=r"(r1), "=r"(r2), "=r"(r3) : "r"(addr));
}
__device__ __forceinline__ void ldm_x2(uint32_t& r0, uint32_t& r1, uint32_t addr) {
    asm volatile("ldmatrix.sync.aligned.m8n8.x2.shared.b16 {%0,%1}, [%2];"
                 : "=r"(r0), "=r"(r1) : "r"(addr));
}

__device__ __forceinline__ void mma_bf16(float& c0, float& c1, float& c2, float& c3,
                                         uint32_t a0, uint32_t a1, uint32_t a2, uint32_t a3,
                                         uint32_t b0, uint32_t b1) {
    asm volatile(
        "mma.sync.aligned.m16n8k16.row.col.f32.bf16.bf16.f32 "
        "{%0,%1,%2,%3}, {%4,%5,%6,%7}, {%8,%9}, {%0,%1,%2,%3};"
        : "+f"(c0), "+f"(c1), "+f"(c2), "+f"(c3)
        : "r"(a0), "r"(a1), "r"(a2), "r"(a3), "r"(b0), "r"(b1));
}

// fp32 pair -> packed bf16 hi pair + packed bf16 residual pair
__device__ __forceinline__ void split_pack(float x, float y, uint32_t& hi, uint32_t& lo) {
    __nv_bfloat16 bx = __float2bfloat16(x), by = __float2bfloat16(y);
    hi = (uint32_t)__bfloat16_as_ushort(bx) | ((uint32_t)__bfloat16_as_ushort(by) << 16);
    __nv_bfloat16 rx = __float2bfloat16(x - __bfloat162float(bx));
    __nv_bfloat16 ry = __float2bfloat16(y - __bfloat162float(by));
    lo = (uint32_t)__bfloat16_as_ushort(rx) | ((uint32_t)__bfloat16_as_ushort(ry) << 16);
}

// ---------------------------------------------------------------------------
// Fused-split tensor-core GEMM: C = (Ahi+Alo)[M,K] @ (Bhi+Blo)^T[N,K] + bias
// One K pipeline; per fragment pair 3 MMAs (hh, lh, hl). CTA 128x128, 8 warps
// (2x4) of 64x32, BK=32, 3-stage cp.async pipeline.
// Stage holds Ahi|Alo|Bhi|Blo tiles (128x(32+8pad) halves each = 10240 B).
// OMODE: 0 = fp32 out, 1 = bf16 hi/lo split out.
// ---------------------------------------------------------------------------
#define STG_BYTES 40960
#define MMA_SMEM  (3*STG_BYTES)   // 122880 B

template<int OMODE, bool RELU>
__device__ __forceinline__ void mma_gemm_body(
    const __nv_bfloat16* __restrict__ Ahi, const __nv_bfloat16* __restrict__ Alo,
    const __nv_bfloat16* __restrict__ Bhi, const __nv_bfloat16* __restrict__ Blo,
    const float* __restrict__ bias, float* __restrict__ C,
    __nv_bfloat16* __restrict__ Chi, __nv_bfloat16* __restrict__ Clo,
    int M, int N, int K)
{
    extern __shared__ char smem[];
    const uint32_t sb = smem_u32(smem);
    const int tid  = threadIdx.x;         // 256
    const int wid  = tid >> 5;
    const int lane = tid & 31;
    const int wm   = (wid & 1) * 64;
    const int wn   = (wid >> 1) * 32;
    const int m0 = blockIdx.y * 128;
    const int n0 = blockIdx.x * 128;

    const int S = K >> 5;                 // K=32 stages

    float acc[4][4][4];
    #pragma unroll
    for (int i = 0; i < 4; i++)
        #pragma unroll
        for (int j = 0; j < 4; j++)
            #pragma unroll
            for (int e = 0; e < 4; e++) acc[i][j][e] = 0.f;

    auto load_stage = [&](int st) {
        const int k0 = st << 5;
        const uint32_t base = sb + (st % 3) * STG_BYTES;
        #pragma unroll
        for (int i = 0; i < 2; i++) {
            int c = tid + i*256;                   // [0,512)
            int row = c >> 2, g = c & 3;
            uint32_t o = row*80 + g*16;
            size_t ga = (size_t)(m0 + row)*K + k0 + g*8;
            size_t gb = (size_t)(n0 + row)*K + k0 + g*8;
            cp_async16(base +         o, Ahi + ga);
            cp_async16(base + 10240 + o, Alo + ga);
            cp_async16(base + 20480 + o, Bhi + gb);
            cp_async16(base + 30720 + o, Blo + gb);
        }
        CP_COMMIT();
    };

    load_stage(0);
    load_stage(1);

    const int a_row = lane & 15;
    const int a_koff = (lane >> 4) * 16;
    const int b_row = lane & 7;
    const int b_koff = ((lane >> 3) & 1) * 16;

    for (int st = 0; st < S; ++st) {
        if (st + 2 < S) load_stage(st + 2);
        CP_WAIT(2);
        __syncthreads();

        const uint32_t base = sb + (st % 3) * STG_BYTES;

        #pragma unroll
        for (int ks = 0; ks < 2; ++ks) {
            uint32_t ah[4][4], al[4][4], bh[4][2], bl[4][2];
            #pragma unroll
            for (int mi = 0; mi < 4; ++mi) {
                uint32_t aa = base + (wm + mi*16 + a_row)*80 + ks*32 + a_koff;
                ldm_x4(ah[mi][0], ah[mi][1], ah[mi][2], ah[mi][3], aa);
                ldm_x4(al[mi][0], al[mi][1], al[mi][2], al[mi][3], aa + 10240);
            }
            #pragma unroll
            for (int ni = 0; ni < 4; ++ni) {
                uint32_t ba = base + 20480 + (wn + ni*8 + b_row)*80 + ks*32 + b_koff;
                ldm_x2(bh[ni][0], bh[ni][1], ba);
                ldm_x2(bl[ni][0], bl[ni][1], ba + 10240);
            }
            #pragma unroll
            for (int mi = 0; mi < 4; ++mi)
                #pragma unroll
                for (int ni = 0; ni < 4; ++ni) {
                    mma_bf16(acc[mi][ni][0], acc[mi][ni][1], acc[mi][ni][2], acc[mi][ni][3],
                             ah[mi][0], ah[mi][1], ah[mi][2], ah[mi][3], bh[ni][0], bh[ni][1]);
                    mma_bf16(acc[mi][ni][0], acc[mi][ni][1], acc[mi][ni][2], acc[mi][ni][3],
                             al[mi][0], al[mi][1], al[mi][2], al[mi][3], bh[ni][0], bh[ni][1]);
                    mma_bf16(acc[mi][ni][0], acc[mi][ni][1], acc[mi][ni][2], acc[mi][ni][3],
                             ah[mi][0], ah[mi][1], ah[mi][2], ah[mi][3], bl[ni][0], bl[ni][1]);
                }
        }
        __syncthreads();
    }

    const int tg = lane >> 2;
    const int tc = (lane & 3) * 2;
    #pragma unroll
    for (int ni = 0; ni < 4; ++ni) {
        const int col = n0 + wn + ni*8 + tc;
        const float bz0 = bias[col], bz1 = bias[col + 1];
        #pragma unroll
        for (int mi = 0; mi < 4; ++mi) {
            const int row = m0 + wm + mi*16 + tg;
            float v0 = acc[mi][ni][0] + bz0, v1 = acc[mi][ni][1] + bz1;
            float v2 = acc[mi][ni][2] + bz0, v3 = acc[mi][ni][3] + bz1;
            if (RELU) {
                v0 = fmaxf(v0, 0.f); v1 = fmaxf(v1, 0.f);
                v2 = fmaxf(v2, 0.f); v3 = fmaxf(v3, 0.f);
            }
            if (OMODE == 0) {
                *reinterpret_cast<float2*>(C + (size_t)row*N + col) = make_float2(v0, v1);
                *reinterpret_cast<float2*>(C + (size_t)(row + 8)*N + col) = make_float2(v2, v3);
            } else {
                uint32_t h0, l0, h1, l1;
                split_pack(v0, v1, h0, l0);
                split_pack(v2, v3, h1, l1);
                *reinterpret_cast<uint32_t*>(Chi + (size_t)row*N + col) = h0;
                *reinterpret_cast<uint32_t*>(Clo + (size_t)row*N + col) = l0;
                *reinterpret_cast<uint32_t*>(Chi + (size_t)(row + 8)*N + col) = h1;
                *reinterpret_cast<uint32_t*>(Clo + (size_t)(row + 8)*N + col) = l1;
            }
        }
    }
}

template<int OMODE, bool RELU>
__global__ void __launch_bounds__(256) mma_gemm_kernel(
    const __nv_bfloat16* __restrict__ Ahi, const __nv_bfloat16* __restrict__ Alo,
    const __nv_bfloat16* __restrict__ Bhi, const __nv_bfloat16* __restrict__ Blo,
    const float* __restrict__ bias, float* __restrict__ C,
    __nv_bfloat16* __restrict__ Chi, __nv_bfloat16* __restrict__ Clo,
    int M, int N, int K)
{
    mma_gemm_body<OMODE, RELU>(Ahi, Alo, Bhi, Blo, bias, C, Chi, Clo, M, N, K);
}

__global__ void __launch_bounds__(256) mma_gemm_qkv_kernel(
    const __nv_bfloat16* __restrict__ Ahi, const __nv_bfloat16* __restrict__ Alo,
    const __nv_bfloat16* __restrict__ Whi, const __nv_bfloat16* __restrict__ Wlo,
    const float* __restrict__ bq, const float* __restrict__ bk, const float* __restrict__ bv,
    float* __restrict__ q, float* __restrict__ k, float* __restrict__ v)
{
    const int z = blockIdx.z;
    const size_t woff = (size_t)z * DMODEL * DMODEL;
    const float* bias = (z == 0) ? bq : (z == 1) ? bk : bv;
    float* C = (z == 0) ? q : (z == 1) ? k : v;
    mma_gemm_body<0, false>(Ahi, Alo, Whi + woff, Wlo + woff, bias, C,
                            nullptr, nullptr, NTOK, DMODEL, DMODEL);
}

// ---------------------------------------------------------------------------
// Weight transpose + split: W[K,N] fp32 -> Whi/Wlo[N,K] bf16. z = layer.
// ---------------------------------------------------------------------------
__global__ void wconv_t_kernel(const float* __restrict__ W, __nv_bfloat16* __restrict__ Whi,
                               __nv_bfloat16* __restrict__ Wlo, int K, int N,
                               size_t strideW, size_t strideO) {
    __shared__ float t[32][33];
    const int l = blockIdx.z;
    W += (size_t)l * strideW; Whi += (size_t)l * strideO; Wlo += (size_t)l * strideO;
    const int tx = threadIdx.x & 31, ty = threadIdx.x >> 5;
    const int kb = blockIdx.y * 32, nb = blockIdx.x * 32;
    #pragma unroll
    for (int i = ty; i < 32; i += 8)
        t[i][tx] = W[(size_t)(kb + i)*N + nb + tx];
    __syncthreads();
    #pragma unroll
    for (int i = ty; i < 32; i += 8) {
        float x = t[tx][i];
        __nv_bfloat16 h = __float2bfloat16(x);
        __nv_bfloat16 lo = __float2bfloat16(x - __bfloat162float(h));
        size_t o = (size_t)(nb + i)*K + kb + tx;
        Whi[o] = h; Wlo[o] = lo;
    }
}

// ---------------------------------------------------------------------------
// Embedding: h = emb[x]*sqrt(D) + pos; also emit bf16 hi/lo split.
// One thread = 4 consecutive elements.
// ---------------------------------------------------------------------------
__global__ void embed_kernel(const int* __restrict__ x, const float* __restrict__ emb,
                             const float* __restrict__ pos) {
    int i4 = blockIdx.x * blockDim.x + threadIdx.x;    // [0, NTOK*DMODEL/4)
    int idx = i4 * 4;
    int t = idx >> 9;
    int d = idx & 511;
    int s = t & (SEQ-1);
    int tok = x[t];
    float4 e = *reinterpret_cast<const float4*>(&emb[(size_t)tok*DMODEL + d]);
    float4 p = *reinterpret_cast<const float4*>(&pos[(size_t)s*DMODEL + d]);
    float4 hv = make_float4(e.x*SQRT_D + p.x, e.y*SQRT_D + p.y,
                            e.z*SQRT_D + p.z, e.w*SQRT_D + p.w);
    *reinterpret_cast<float4*>(&g_h[idx]) = hv;
    uint32_t h0, l0, h1, l1;
    split_pack(hv.x, hv.y, h0, l0);
    split_pack(hv.z, hv.w, h1, l1);
    reinterpret_cast<uint2*>(g_h_hi)[i4] = make_uint2(h0, h1);
    reinterpret_cast<uint2*>(g_h_lo)[i4] = make_uint2(l0, l1);
}

// ---------------------------------------------------------------------------
// QE-skew on tensor cores: SK[bh][i][j] = q_i . E[1023-i+j] (j in [0,i])
// One block = (bh, 64 query rows); 4 warps x 16 rows; 64-row E tiles.
// ---------------------------------------------------------------------------
#define QE2_SMEM (4 * 64*72 * 2)   // Qhi,Qlo,Ehi,Elo = 36864 B

__global__ void __launch_bounds__(128) qe_skew2_kernel(
    const float* __restrict__ q, const float* __restrict__ E, float* __restrict__ SK)
{
    extern __shared__ char smembuf[];
    const uint32_t sb = smem_u32(smembuf);
    __nv_bfloat16* smh = reinterpret_cast<__nv_bfloat16*>(smembuf);
    const int QHI = 0, QLO = 4608, EHI = 9216, ELO = 13824;   // half-elem offsets

    const int bh = blockIdx.y;
    const int b  = bh >> 3;
    const int h  = bh & 7;
    const int i0 = blockIdx.x * 64;
    const int tid  = threadIdx.x;      // 128
    const int wid  = tid >> 5;
    const int lane = tid & 31;
    const int tok0 = b * SEQ;
    const int hoff = h * DHEAD;
    const int wq = wid * 16;

    // load + split Q tile (64x64)
    #pragma unroll
    for (int t = 0; t < 8; t++) {
        int f = tid + t*128;
        int r = f >> 4, d4 = (f & 15) * 4;
        float4 qv = *reinterpret_cast<const float4*>(&q[(size_t)(tok0 + i0 + r)*DMODEL + hoff + d4]);
        uint32_t h0, l0, h1, l1;
        split_pack(qv.x, qv.y, h0, l0);
        split_pack(qv.z, qv.w, h1, l1);
        int off = r*72 + d4;
        *reinterpret_cast<uint2*>(smh + QHI + off) = make_uint2(h0, h1);
        *reinterpret_cast<uint2*>(smh + QLO + off) = make_uint2(l0, l1);
    }

    float* skb = SK + ((size_t)bh << 20);
    const int row0 = i0 + wq + (lane >> 2);
    const int qc = (lane & 3) * 2;

    const uint32_t a_addr0 = sb + ((uint32_t)((wq + (lane & 15))*72 + (lane >> 4)*8)) * 2;
    const uint32_t b_roff  = ((uint32_t)((lane & 7)*72 + ((lane >> 3) & 1)*8)) * 2;

    const int mt_lo = ((960 - i0) >> 6) << 6;

    for (int mt = mt_lo; mt < 1024; mt += 64) {
        __syncthreads();
        // load + split E tile (64 m-rows x 64)
        #pragma unroll
        for (int t = 0; t < 8; t++) {
            int f = tid + t*128;
            int r = f >> 4, d4 = (f & 15) * 4;
            float4 ev = *reinterpret_cast<const float4*>(&E[(size_t)(mt + r)*DHEAD + d4]);
            uint32_t h0, l0, h1, l1;
            split_pack(ev.x, ev.y, h0, l0);
            split_pack(ev.z, ev.w, h1, l1);
            int off = r*72 + d4;
            *reinterpret_cast<uint2*>(smh + EHI + off) = make_uint2(h0, h1);
            *reinterpret_cast<uint2*>(smh + ELO + off) = make_uint2(l0, l1);
        }
        __syncthreads();

        float s[8][4];
        #pragma unroll
        for (int n = 0; n < 8; n++)
            #pragma unroll
            for (int e = 0; e < 4; e++) s[n][e] = 0.f;

        #pragma unroll
        for (int kt = 0; kt < 4; kt++) {
            uint32_t ah[4], al[4];
            ldm_x4(ah[0], ah[1], ah[2], ah[3], a_addr0 + kt*32);
            ldm_x4(al[0], al[1], al[2], al[3], a_addr0 + QLO*2 + kt*32);
            #pragma unroll
            for (int n = 0; n < 8; n++) {
                uint32_t ba = sb + EHI*2 + (uint32_t)(8*n*72)*2 + b_roff + kt*32;
                uint32_t bh0, bh1, bl0, bl1;
                ldm_x2(bh0, bh1, ba);
                ldm_x2(bl0, bl1, ba + (ELO - EHI)*2);
                mma_bf16(s[n][0], s[n][1], s[n][2], s[n][3], ah[0], ah[1], ah[2], ah[3], bh0, bh1);
                mma_bf16(s[n][0], s[n][1], s[n][2], s[n][3], al[0], al[1], al[2], al[3], bh0, bh1);
                mma_bf16(s[n][0], s[n][1], s[n][2], s[n][3], ah[0], ah[1], ah[2], ah[3], bl0, bl1);
            }
        }

        // skewed scatter: QE[i][m] -> SK[i][j = m-1023+i]
        #pragma unroll
        for (int n = 0; n < 8; n++) {
            int m = mt + 8*n + qc;
            int j0 = m - 1023 + row0;
            if (j0 >= 0)       { skb[((size_t)row0 << 10) + j0] = s[n][0];
                                 skb[((size_t)row0 << 10) + j0 + 1] = s[n][1]; }
            else if (j0 == -1)   skb[((size_t)row0 << 10)] = s[n][1];
            int j1 = j0 + 8;
            int r1 = row0 + 8;
            if (j1 >= 0)       { skb[((size_t)r1 << 10) + j1] = s[n][2];
                                 skb[((size_t)r1 << 10) + j1 + 1] = s[n][3]; }
            else if (j1 == -1)   skb[((size_t)r1 << 10)] = s[n][3];
        }
    }
}

// ---------------------------------------------------------------------------
// Flash attention on tensor cores (mma.sync, bf16x3 split).
// Writes bf16 hi/lo split output directly (consumed by Wo GEMM).
// ---------------------------------------------------------------------------
#define AT2_SMEM (6 * 64*72 * 2)   // 55296 B

__global__ void __launch_bounds__(128) attention2_kernel(
    const float* __restrict__ q, const float* __restrict__ k,
    const float* __restrict__ v, const float* __restrict__ SK,
    __nv_bfloat16* __restrict__ Ohi, __nv_bfloat16* __restrict__ Olo)
{
    extern __shared__ char smembuf[];
    const uint32_t sb = smem_u32(smembuf);
    __nv_bfloat16* smh = reinterpret_cast<__nv_bfloat16*>(smembuf);
    const int QHI = 0, QLO = 4608, KHI = 9216, KLO = 13824, VTH = 18432, VTL = 23040;

    const int bh = blockIdx.y;
    const int b  = bh >> 3;
    const int h  = bh & 7;
    const int i0 = blockIdx.x * 64;
    const int tid  = threadIdx.x;      // 128
    const int wid  = tid >> 5;
    const int lane = tid & 31;
    const int tok0 = b * SEQ;
    const int hoff = h * DHEAD;
    const int wq = wid * 16;

    #pragma unroll
    for (int t = 0; t < 8; t++) {
        int f = tid + t*128;
        int r = f >> 4, d4 = (f & 15) * 4;
        float4 qv = *reinterpret_cast<const float4*>(&q[(size_t)(tok0 + i0 + r)*DMODEL + hoff + d4]);
        uint32_t h0, l0, h1, l1;
        split_pack(qv.x, qv.y, h0, l0);
        split_pack(qv.z, qv.w, h1, l1);
        int off = r*72 + d4;
        *reinterpret_cast<uint2*>(smh + QHI + off) = make_uint2(h0, h1);
        *reinterpret_cast<uint2*>(smh + QLO + off) = make_uint2(l0, l1);
    }

    float m_i[2] = {-1e30f, -1e30f}, l_i[2] = {0.f, 0.f};
    float acc[8][4];
    #pragma unroll
    for (int n = 0; n < 8; n++)
        #pragma unroll
        for (int e = 0; e < 4; e++) acc[n][e] = 0.f;

    const float* skb = SK + ((size_t)bh << 20);
    const int row0 = i0 + wq + (lane >> 2);
    const int qc = (lane & 3) * 2;

    const uint32_t a_addr0 = sb + ((uint32_t)((wq + (lane & 15))*72 + (lane >> 4)*8)) * 2;
    const uint32_t b_roff  = ((uint32_t)((lane & 7)*72 + ((lane >> 3) & 1)*8)) * 2;

    for (int jt = 0; jt < 16; jt++) {
        const int j0 = jt * 64;
        __syncthreads();
        #pragma unroll
        for (int t = 0; t < 8; t++) {
            int f = tid + t*128;
            int r = f >> 4, d4 = (f & 15) * 4;
            float4 kv = *reinterpret_cast<const float4*>(&k[(size_t)(tok0 + j0 + r)*DMODEL + hoff + d4]);
            uint32_t h0, l0, h1, l1;
            split_pack(kv.x, kv.y, h0, l0);
            split_pack(kv.z, kv.w, h1, l1);
            int off = r*72 + d4;
            *reinterpret_cast<uint2*>(smh + KHI + off) = make_uint2(h0, h1);
            *reinterpret_cast<uint2*>(smh + KLO + off) = make_uint2(l0, l1);

            float4 vv = *reinterpret_cast<const float4*>(&v[(size_t)(tok0 + j0 + r)*DMODEL + hoff + d4]);
            float ve[4] = {vv.x, vv.y, vv.z, vv.w};
            #pragma unroll
            for (int e = 0; e < 4; e++) {
                __nv_bfloat16 bh16 = __float2bfloat16(ve[e]);
                __nv_bfloat16 bl16 = __float2bfloat16(ve[e] - __bfloat162float(bh16));
                smh[VTH + (d4+e)*72 + r] = bh16;
                smh[VTL + (d4+e)*72 + r] = bl16;
            }
        }
        __syncthreads();

        float s[8][4];
        #pragma unroll
        for (int n = 0; n < 8; n++)
            #pragma unroll
            for (int e = 0; e < 4; e++) s[n][e] = 0.f;

        #pragma unroll
        for (int kt = 0; kt < 4; kt++) {
            uint32_t ah[4], al[4];
            ldm_x4(ah[0], ah[1], ah[2], ah[3], a_addr0 + kt*32);
            ldm_x4(al[0], al[1], al[2], al[3], a_addr0 + QLO*2 + kt*32);
            #pragma unroll
            for (int n = 0; n < 8; n++) {
                uint32_t ba = sb + KHI*2 + (uint32_t)(8*n*72)*2 + b_roff + kt*32;
                uint32_t bh0, bh1, bl0, bl1;
                ldm_x2(bh0, bh1, ba);
                ldm_x2(bl0, bl1, ba + (KLO - KHI)*2);
                mma_bf16(s[n][0], s[n][1], s[n][2], s[n][3], ah[0], ah[1], ah[2], ah[3], bh0, bh1);
                mma_bf16(s[n][0], s[n][1], s[n][2], s[n][3], ah[0], ah[1], ah[2], ah[3], bl0, bl1);
                mma_bf16(s[n][0], s[n][1], s[n][2], s[n][3], al[0], al[1], al[2], al[3], bh0, bh1);
            }
        }

        #pragma unroll
        for (int n = 0; n < 8; n++) {
            int jc = j0 + 8*n + qc;
            const float* p0 = skb + ((size_t)row0 << 10) + jc;
            const float* p1 = p0 + (8 << 10);
            if (jc     <= row0)     s[n][0] += p0[0];
            if (jc + 1 <= row0)     s[n][1] += p0[1];
            if (jc     <= row0 + 8) s[n][2] += p1[0];
            if (jc + 1 <= row0 + 8) s[n][3] += p1[1];
            #pragma unroll
            for (int e = 0; e < 4; e++) s[n][e] *= INV_SQRT_DH;
        }

        #pragma unroll
        for (int rr = 0; rr < 2; rr++) {
            float mx = -1e30f;
            #pragma unroll
            for (int n = 0; n < 8; n++) {
                mx = fmaxf(mx, s[n][2*rr]);
                mx = fmaxf(mx, s[n][2*rr + 1]);
            }
            mx = fmaxf(mx, __shfl_xor_sync(0xffffffffu, mx, 1));
            mx = fmaxf(mx, __shfl_xor_sync(0xffffffffu, mx, 2));
            float mn = fmaxf(m_i[rr], mx);
            float alpha = __expf(m_i[rr] - mn);
            float ps = 0.f;
            #pragma unroll
            for (int n = 0; n < 8; n++) {
                float p0 = __expf(s[n][2*rr]     - mn);
                float p1 = __expf(s[n][2*rr + 1] - mn);
                s[n][2*rr] = p0; s[n][2*rr + 1] = p1;
                ps += p0 + p1;
            }
            ps += __shfl_xor_sync(0xffffffffu, ps, 1);
            ps += __shfl_xor_sync(0xffffffffu, ps, 2);
            l_i[rr] = l_i[rr] * alpha + ps;
            m_i[rr] = mn;
            #pragma unroll
            for (int dn = 0; dn < 8; dn++) {
                acc[dn][2*rr]     *= alpha;
                acc[dn][2*rr + 1] *= alpha;
            }
        }

        uint32_t ph[8][2], pl[8][2];
        #pragma unroll
        for (int n = 0; n < 8; n++) {
            split_pack(s[n][0], s[n][1], ph[n][0], pl[n][0]);
            split_pack(s[n][2], s[n][3], ph[n][1], pl[n][1]);
        }

        #pragma unroll
        for (int kt = 0; kt < 4; kt++) {
            uint32_t ah0 = ph[2*kt][0], ah1 = ph[2*kt][1], ah2 = ph[2*kt+1][0], ah3 = ph[2*kt+1][1];
            uint32_t al0 = pl[2*kt][0], al1 = pl[2*kt][1], al2 = pl[2*kt+1][0], al3 = pl[2*kt+1][1];
            #pragma unroll
            for (int dn = 0; dn < 8; dn++) {
                uint32_t ba = sb + VTH*2 + (uint32_t)(8*dn*72)*2 + b_roff + kt*32;
                uint32_t bh0, bh1, bl0, bl1;
                ldm_x2(bh0, bh1, ba);
                ldm_x2(bl0, bl1, ba + (VTL - VTH)*2);
                mma_bf16(acc[dn][0], acc[dn][1], acc[dn][2], acc[dn][3], ah0, ah1, ah2, ah3, bh0, bh1);
                mma_bf16(acc[dn][0], acc[dn][1], acc[dn][2], acc[dn][3], al0, al1, al2, al3, bh0, bh1);
                mma_bf16(acc[dn][0], acc[dn][1], acc[dn][2], acc[dn][3], ah0, ah1, ah2, ah3, bl0, bl1);
            }
        }
    }

    // normalize + split-store
    #pragma unroll
    for (int rr = 0; rr < 2; rr++) {
        float inv = 1.f / l_i[rr];
        int row = row0 + rr*8;
        #pragma unroll
        for (int dn = 0; dn < 8; dn++) {
            float o0 = acc[dn][2*rr] * inv, o1 = acc[dn][2*rr + 1] * inv;
            uint32_t hi, lo;
            split_pack(o0, o1, hi, lo);
            size_t oaddr = (size_t)(tok0 + row)*DMODEL + hoff + 8*dn + qc;
            *reinterpret_cast<uint32_t*>(Ohi + oaddr) = hi;
            *reinterpret_cast<uint32_t*>(Olo + oaddr) = lo;
        }
    }
}

// ---------------------------------------------------------------------------
// y = LayerNorm(a + b) * scale + bias; emits fp32 y and bf16 hi/lo split.
// 128 threads/token; thread owns 4 consecutive dims.
// ---------------------------------------------------------------------------
__global__ void add_ln_kernel(const float* __restrict__ a, const float* __restrict__ b,
                              const float* __restrict__ scale, const float* __restrict__ bias,
                              float* __restrict__ y,
                              __nv_bfloat16* __restrict__ yhi, __nv_bfloat16* __restrict__ ylo) {
    const int t = blockIdx.x;
    const int tid = threadIdx.x;       // 128
    const int d4 = tid * 4;
    const size_t base = (size_t)t*DMODEL + d4;
    float4 av = *reinterpret_cast<const float4*>(a + base);
    float4 bv = *reinterpret_cast<const float4*>(b + base);
    float x[4] = {av.x + bv.x, av.y + bv.y, av.z + bv.z, av.w + bv.w};
    float sum = x[0] + x[1] + x[2] + x[3];
    __shared__ float red[4];
    #pragma unroll
    for (int o = 16; o > 0; o >>= 1) sum += __shfl_xor_sync(0xffffffffu, sum, o);
    if ((tid & 31) == 0) red[tid >> 5] = sum;
    __syncthreads();
    sum = red[0] + red[1] + red[2] + red[3];
    const float mu = sum * (1.f/512.f);
    float vs = 0.f;
    #pragma unroll
    for (int i = 0; i < 4; i++) { float dd = x[i] - mu; vs = fmaf(dd, dd, vs); }
    #pragma unroll
    for (int o = 16; o > 0; o >>= 1) vs += __shfl_xor_sync(0xffffffffu, vs, o);
    __shared__ float red2[4];
    if ((tid & 31) == 0) red2[tid >> 5] = vs;
    __syncthreads();
    vs = red2[0] + red2[1] + red2[2] + red2[3];
    const float rstd = rsqrtf(vs * (1.f/512.f) + 1e-6f);
    float o[4];
    #pragma unroll
    for (int i = 0; i < 4; i++)
        o[i] = (x[i] - mu) * rstd * scale[d4 + i] + bias[d4 + i];
    *reinterpret_cast<float4*>(y + base) = make_float4(o[0], o[1], o[2], o[3]);
    uint32_t h0, l0, h1, l1;
    split_pack(o[0], o[1], h0, l0);
    split_pack(o[2], o[3], h1, l1);
    *reinterpret_cast<uint2*>(yhi + base) = make_uint2(h0, h1);
    *reinterpret_cast<uint2*>(ylo + base) = make_uint2(l0, l1);
}

// ---------------------------------------------------------------------------
// out[b,o] = tanh(h[b,0,:] . Wf[:,o] + bf[o])
// ---------------------------------------------------------------------------
__global__ void head_kernel(const float* __restrict__ Wf, const float* __restrict__ bf,
                            float* __restrict__ out) {
    const int w = threadIdx.x >> 5;
    const int lane = threadIdx.x & 31;
    const int b = w >> 1, o = w & 1;
    const float* hr = g_h + (size_t)b*SEQ*DMODEL;
    float sum = 0.f;
    #pragma unroll
    for (int d = lane; d < DMODEL; d += 32)
        sum = fmaf(hr[d], Wf[d*2 + o], sum);
    #pragma unroll
    for (int off = 16; off > 0; off >>= 1) sum += __shfl_xor_sync(0xffffffffu, sum, off);
    if (lane == 0) out[b*2 + o] = tanhf(sum + bf[o]);
}

// ---------------------------------------------------------------------------
// Launch
// ---------------------------------------------------------------------------
extern "C" void kernel_launch(void* const* d_in, const int* in_sizes, int n_in,
                              void* d_out, int out_size) {
    const int*   x    = (const int*)  d_in[0];
    const float* emb  = (const float*)d_in[1];
    const float* pos  = (const float*)d_in[2];
    const float* Wq   = (const float*)d_in[3];
    const float* bq   = (const float*)d_in[4];
    const float* Wk   = (const float*)d_in[5];
    const float* bk   = (const float*)d_in[6];
    const float* Wv   = (const float*)d_in[7];
    const float* bv   = (const float*)d_in[8];
    const float* Wo   = (const float*)d_in[9];
    const float* bo   = (const float*)d_in[10];
    const float* E    = (const float*)d_in[11];
    const float* W1   = (const float*)d_in[12];
    const float* b1   = (const float*)d_in[13];
    const float* W2   = (const float*)d_in[14];
    const float* b2   = (const float*)d_in[15];
    const float* ln1s = (const float*)d_in[16];
    const float* ln1b = (const float*)d_in[17];
    const float* ln2s = (const float*)d_in[18];
    const float* ln2b = (const float*)d_in[19];
    const float* Wf   = (const float*)d_in[20];
    const float* bf   = (const float*)d_in[21];
    float* out = (float*)d_out;

    float *h, *qb, *kb, *vb, *h1, *ffn, *sk;
    cudaGetSymbolAddress((void**)&h,   g_h);
    cudaGetSymbolAddress((void**)&qb,  g_q);
    cudaGetSymbolAddress((void**)&kb,  g_k);
    cudaGetSymbolAddress((void**)&vb,  g_v);
    cudaGetSymbolAddress((void**)&h1,  g_h1);
    cudaGetSymbolAddress((void**)&ffn, g_ffn);
    cudaGetSymbolAddress((void**)&sk,  g_sk);

    __nv_bfloat16 *hhi, *hlo, *athi, *atlo, *h1hi, *h1lo, *mdhi, *mdlo;
    __nv_bfloat16 *w4h, *w4l, *w1h, *w1l, *w2h, *w2l;
    cudaGetSymbolAddress((void**)&hhi,  g_h_hi);
    cudaGetSymbolAddress((void**)&hlo,  g_h_lo);
    cudaGetSymbolAddress((void**)&athi, g_attn_hi);
    cudaGetSymbolAddress((void**)&atlo, g_attn_lo);
    cudaGetSymbolAddress((void**)&h1hi, g_h1_hi);
    cudaGetSymbolAddress((void**)&h1lo, g_h1_lo);
    cudaGetSymbolAddress((void**)&mdhi, g_mid_hi);
    cudaGetSymbolAddress((void**)&mdlo, g_mid_lo);
    cudaGetSymbolAddress((void**)&w4h, g_w4_hi);
    cudaGetSymbolAddress((void**)&w4l, g_w4_lo);
    cudaGetSymbolAddress((void**)&w1h, g_w1_hi);
    cudaGetSymbolAddress((void**)&w1l, g_w1_lo);
    cudaGetSymbolAddress((void**)&w2h, g_w2_hi);
    cudaGetSymbolAddress((void**)&w2l, g_w2_lo);

    cudaFuncSetAttribute(attention2_kernel, cudaFuncAttributeMaxDynamicSharedMemorySize, AT2_SMEM);
    cudaFuncSetAttribute(qe_skew2_kernel,   cudaFuncAttributeMaxDynamicSharedMemorySize, QE2_SMEM);
    cudaFuncSetAttribute((const void*)mma_gemm_kernel<0,false>, cudaFuncAttributeMaxDynamicSharedMemorySize, MMA_SMEM);
    cudaFuncSetAttribute((const void*)mma_gemm_kernel<1,true>,  cudaFuncAttributeMaxDynamicSharedMemorySize, MMA_SMEM);
    cudaFuncSetAttribute((const void*)mma_gemm_qkv_kernel,      cudaFuncAttributeMaxDynamicSharedMemorySize, MMA_SMEM);

    const size_t SZ = (size_t)DMODEL * DMODEL;      // 262144

    wconv_t_kernel<<<dim3(16,16,NLAYER), 256>>>(Wq, w4h + 0*SZ, w4l + 0*SZ, DMODEL, DMODEL, SZ, 4*SZ);
    wconv_t_kernel<<<dim3(16,16,NLAYER), 256>>>(Wk, w4h + 1*SZ, w4l + 1*SZ, DMODEL, DMODEL, SZ, 4*SZ);
    wconv_t_kernel<<<dim3(16,16,NLAYER), 256>>>(Wv, w4h + 2*SZ, w4l + 2*SZ, DMODEL, DMODEL, SZ, 4*SZ);
    wconv_t_kernel<<<dim3(16,16,NLAYER), 256>>>(Wo, w4h + 3*SZ, w4l + 3*SZ, DMODEL, DMODEL, SZ, 4*SZ);
    wconv_t_kernel<<<dim3(64,16,NLAYER), 256>>>(W1, w1h, w1l, DMODEL, DINNER,
                                                (size_t)DMODEL*DINNER, (size_t)DINNER*DMODEL);
    wconv_t_kernel<<<dim3(16,64,NLAYER), 256>>>(W2, w2h, w2l, DINNER, DMODEL,
                                                (size_t)DINNER*DMODEL, (size_t)DMODEL*DINNER);

    embed_kernel<<<NTOK*DMODEL/4/256, 256>>>(x, emb, pos);

    for (int l = 0; l < NLAYER; l++) {
        const __nv_bfloat16* l4h = w4h + (size_t)l*4*SZ;
        const __nv_bfloat16* l4l = w4l + (size_t)l*4*SZ;

        mma_gemm_qkv_kernel<<<dim3(4,32,3), 256, MMA_SMEM>>>(hhi, hlo, l4h, l4l,
            bq + l*DMODEL, bk + l*DMODEL, bv + l*DMODEL, qb, kb, vb);

        qe_skew2_kernel<<<dim3(16,32), 128, QE2_SMEM>>>(qb, E + (size_t)l*SEQ*DHEAD, sk);
        attention2_kernel<<<dim3(16,32), 128, AT2_SMEM>>>(qb, kb, vb, sk, athi, atlo);

        mma_gemm_kernel<0,false><<<dim3(4,32), 256, MMA_SMEM>>>(athi, atlo, l4h + 3*SZ, l4l + 3*SZ,
            bo + l*DMODEL, ffn, nullptr, nullptr, NTOK, DMODEL, DMODEL);
        add_ln_kernel<<<NTOK, 128>>>(ffn, h, ln1s + l*DMODEL, ln1b + l*DMODEL, h1, h1hi, h1lo);

        mma_gemm_kernel<1,true><<<dim3(16,32), 256, MMA_SMEM>>>(h1hi, h1lo,
            w1h + (size_t)l*DINNER*DMODEL, w1l + (size_t)l*DINNER*DMODEL,
            b1 + l*DINNER, nullptr, mdhi, mdlo, NTOK, DINNER, DMODEL);

        mma_gemm_kernel<0,false><<<dim3(4,32), 256, MMA_SMEM>>>(mdhi, mdlo,
            w2h + (size_t)l*DMODEL*DINNER, w2l + (size_t)l*DMODEL*DINNER,
            b2 + l*DMODEL, ffn, nullptr, nullptr, NTOK, DMODEL, DINNER);
        add_ln_kernel<<<NTOK, 128>>>(h1, ffn, ln2s + l*DMODEL, ln2b + l*DMODEL, h, hhi, hlo);
    }

    head_kernel<<<1, 256>>>(Wf, bf, out);
}

// round 7
// speedup vs baseline: 4.5588x; 1.1360x over previous
#include <cuda_runtime.h>
#include <cuda_bf16.h>
#include <math.h>
#include <stdint.h>

// ---------------------------------------------------------------------------
// Problem constants
// ---------------------------------------------------------------------------
#define BATCH 4
#define SEQ   1024
#define DMODEL 512
#define DINNER 2048
#define NHEAD 8
#define DHEAD 64
#define NLAYER 6
#define NTOK (BATCH*SEQ)          // 4096
#define SQRT_D 22.627416997969522f
#define INV_SQRT_DH 0.125f

// ---------------------------------------------------------------------------
// Scratch (device globals: no allocations allowed)
// ---------------------------------------------------------------------------
__device__ float g_h   [NTOK*DMODEL];
__device__ float g_h1  [NTOK*DMODEL];
__device__ float g_ffn [NTOK*DMODEL];
__device__ float g_sk  [32u*1024u*1024u];   // SK[bh][i][j] = q_i . E[1023-i+j], j<=i

// bf16 split operand buffers
__device__ __nv_bfloat16 g_h_hi   [NTOK*DMODEL];
__device__ __nv_bfloat16 g_h_lo   [NTOK*DMODEL];
__device__ __nv_bfloat16 g_q_hi   [NTOK*DMODEL];
__device__ __nv_bfloat16 g_q_lo   [NTOK*DMODEL];
__device__ __nv_bfloat16 g_k_hi   [NTOK*DMODEL];
__device__ __nv_bfloat16 g_k_lo   [NTOK*DMODEL];
__device__ __nv_bfloat16 g_v_hi   [NTOK*DMODEL];
__device__ __nv_bfloat16 g_v_lo   [NTOK*DMODEL];
__device__ __nv_bfloat16 g_attn_hi[NTOK*DMODEL];
__device__ __nv_bfloat16 g_attn_lo[NTOK*DMODEL];
__device__ __nv_bfloat16 g_h1_hi  [NTOK*DMODEL];
__device__ __nv_bfloat16 g_h1_lo  [NTOK*DMODEL];
__device__ __nv_bfloat16 g_mid_hi [NTOK*DINNER];
__device__ __nv_bfloat16 g_mid_lo [NTOK*DINNER];
__device__ __nv_bfloat16 g_e_hi   [NLAYER*SEQ*DHEAD];
__device__ __nv_bfloat16 g_e_lo   [NLAYER*SEQ*DHEAD];

__device__ __nv_bfloat16 g_w4_hi[NLAYER*4*DMODEL*DMODEL];   // q,k,v,o transposed [N,K]
__device__ __nv_bfloat16 g_w4_lo[NLAYER*4*DMODEL*DMODEL];
__device__ __nv_bfloat16 g_w1_hi[NLAYER*DINNER*DMODEL];     // W1^T
__device__ __nv_bfloat16 g_w1_lo[NLAYER*DINNER*DMODEL];
__device__ __nv_bfloat16 g_w2_hi[NLAYER*DMODEL*DINNER];     // W2^T
__device__ __nv_bfloat16 g_w2_lo[NLAYER*DMODEL*DINNER];

// ---------------------------------------------------------------------------
// PTX helpers
// ---------------------------------------------------------------------------
__device__ __forceinline__ uint32_t smem_u32(const void* p) {
    uint32_t a;
    asm("{ .reg .u64 t; cvta.to.shared.u64 t, %1; cvt.u32.u64 %0, t; }" : "=r"(a) : "l"(p));
    return a;
}

__device__ __forceinline__ void cp_async16(uint32_t dst, const void* src) {
    asm volatile("cp.async.cg.shared.global [%0], [%1], 16;" :: "r"(dst), "l"(src));
}
#define CP_COMMIT() asm volatile("cp.async.commit_group;" ::: "memory")
#define CP_WAIT(N)  asm volatile("cp.async.wait_group %0;" :: "n"(N) : "memory")

__device__ __forceinline__ void ldm_x4(uint32_t& r0, uint32_t& r1, uint32_t& r2, uint32_t& r3,
                                       uint32_t addr) {
    asm volatile("ldmatrix.sync.aligned.m8n8.x4.shared.b16 {%0,%1,%2,%3}, [%4];"
                 : "=r"(r0), "=r"(r1), "=r"(r2), "=r"(r3) : "r"(addr));
}
__device__ __forceinline__ void ldm_x4t(uint32_t& r0, uint32_t& r1, uint32_t& r2, uint32_t& r3,
                                        uint32_t addr) {
    asm volatile("ldmatrix.sync.aligned.m8n8.x4.trans.shared.b16 {%0,%1,%2,%3}, [%4];"
                 : "=r"(r0), "=r"(r1), "=r"(r2), "=r"(r3) : "r"(addr));
}

__device__ __forceinline__ void mma_bf16(float& c0, float& c1, float& c2, float& c3,
                                         uint32_t a0, uint32_t a1, uint32_t a2, uint32_t a3,
                                         uint32_t b0, uint32_t b1) {
    asm volatile(
        "mma.sync.aligned.m16n8k16.row.col.f32.bf16.bf16.f32 "
        "{%0,%1,%2,%3}, {%4,%5,%6,%7}, {%8,%9}, {%0,%1,%2,%3};"
        : "+f"(c0), "+f"(c1), "+f"(c2), "+f"(c3)
        : "r"(a0), "r"(a1), "r"(a2), "r"(a3), "r"(b0), "r"(b1));
}

__device__ __forceinline__ void split_pack(float x, float y, uint32_t& hi, uint32_t& lo) {
    __nv_bfloat16 bx = __float2bfloat16(x), by = __float2bfloat16(y);
    hi = (uint32_t)__bfloat16_as_ushort(bx) | ((uint32_t)__bfloat16_as_ushort(by) << 16);
    __nv_bfloat16 rx = __float2bfloat16(x - __bfloat162float(bx));
    __nv_bfloat16 ry = __float2bfloat16(y - __bfloat162float(by));
    lo = (uint32_t)__bfloat16_as_ushort(rx) | ((uint32_t)__bfloat16_as_ushort(ry) << 16);
}

// ---------------------------------------------------------------------------
// Fused-split tensor-core GEMM: C = (Ahi+Alo)[M,K] @ (Bhi+Blo)^T[N,K] + bias
// BK=64, 2-stage cp.async pipeline. CTA 128x128, 8 warps (2x4) of 64x32.
// Stage: Ahi|Alo|Bhi|Blo, each 128 rows x 144B (64 halves + 8pad) = 73728 B.
// OMODE: 0 = fp32 out, 1 = bf16 hi/lo split out.
// ---------------------------------------------------------------------------
#define OPB 18432               // bytes per operand tile (128*144)
#define STG_BYTES (4*OPB)       // 73728
#define MMA_SMEM  (2*STG_BYTES) // 147456

template<int OMODE, bool RELU>
__device__ __forceinline__ void mma_gemm_body(
    const __nv_bfloat16* __restrict__ Ahi, const __nv_bfloat16* __restrict__ Alo,
    const __nv_bfloat16* __restrict__ Bhi, const __nv_bfloat16* __restrict__ Blo,
    const float* __restrict__ bias, float* __restrict__ C,
    __nv_bfloat16* __restrict__ Chi, __nv_bfloat16* __restrict__ Clo,
    int M, int N, int K)
{
    extern __shared__ char smem[];
    const uint32_t sb = smem_u32(smem);
    const int tid  = threadIdx.x;         // 256
    const int wid  = tid >> 5;
    const int lane = tid & 31;
    const int wm   = (wid & 1) * 64;
    const int wn   = (wid >> 1) * 32;
    const int m0 = blockIdx.y * 128;
    const int n0 = blockIdx.x * 128;

    const int S = K >> 6;                 // BK=64 stages

    float acc[4][4][4];
    #pragma unroll
    for (int i = 0; i < 4; i++)
        #pragma unroll
        for (int j = 0; j < 4; j++)
            #pragma unroll
            for (int e = 0; e < 4; e++) acc[i][j][e] = 0.f;

    auto load_stage = [&](int st) {
        const int k0 = st << 6;
        const uint32_t base = sb + (st & 1) * STG_BYTES;
        #pragma unroll
        for (int i = 0; i < 16; i++) {
            int idx = tid + i*256;                 // [0,4096)
            int op = idx >> 10;
            int rem = idx & 1023;
            int r = rem >> 3, g = rem & 7;
            uint32_t dst = base + op*OPB + r*144 + g*16;
            const __nv_bfloat16* src;
            if (op == 0)      src = Ahi + (size_t)(m0 + r)*K + k0 + g*8;
            else if (op == 1) src = Alo + (size_t)(m0 + r)*K + k0 + g*8;
            else if (op == 2) src = Bhi + (size_t)(n0 + r)*K + k0 + g*8;
            else              src = Blo + (size_t)(n0 + r)*K + k0 + g*8;
            cp_async16(dst, src);
        }
        CP_COMMIT();
    };

    load_stage(0);

    const int a_row = lane & 15;
    const int koff16 = (lane >> 4) * 16;

    for (int st = 0; st < S; ++st) {
        if (st + 1 < S) { load_stage(st + 1); CP_WAIT(1); }
        else            { CP_WAIT(0); }
        __syncthreads();

        const uint32_t base = sb + (st & 1) * STG_BYTES;

        #pragma unroll
        for (int ks = 0; ks < 4; ++ks) {
            uint32_t ah[4][4], al[4][4], bh[4][2], bl[4][2];
            #pragma unroll
            for (int mi = 0; mi < 4; ++mi) {
                uint32_t aa = base + (wm + mi*16 + a_row)*144 + ks*32 + koff16;
                ldm_x4(ah[mi][0], ah[mi][1], ah[mi][2], ah[mi][3], aa);
                ldm_x4(al[mi][0], al[mi][1], al[mi][2], al[mi][3], aa + OPB);
            }
            #pragma unroll
            for (int p = 0; p < 2; ++p) {
                uint32_t r0, r1, r2, r3;
                uint32_t ba = base + 2*OPB + (wn + p*16 + a_row)*144 + ks*32 + koff16;
                ldm_x4(r0, r1, r2, r3, ba);
                bh[2*p][0] = r0; bh[2*p][1] = r2; bh[2*p+1][0] = r1; bh[2*p+1][1] = r3;
                ldm_x4(r0, r1, r2, r3, ba + OPB);
                bl[2*p][0] = r0; bl[2*p][1] = r2; bl[2*p+1][0] = r1; bl[2*p+1][1] = r3;
            }
            #pragma unroll
            for (int mi = 0; mi < 4; ++mi)
                #pragma unroll
                for (int ni = 0; ni < 4; ++ni) {
                    mma_bf16(acc[mi][ni][0], acc[mi][ni][1], acc[mi][ni][2], acc[mi][ni][3],
                             ah[mi][0], ah[mi][1], ah[mi][2], ah[mi][3], bh[ni][0], bh[ni][1]);
                    mma_bf16(acc[mi][ni][0], acc[mi][ni][1], acc[mi][ni][2], acc[mi][ni][3],
                             al[mi][0], al[mi][1], al[mi][2], al[mi][3], bh[ni][0], bh[ni][1]);
                    mma_bf16(acc[mi][ni][0], acc[mi][ni][1], acc[mi][ni][2], acc[mi][ni][3],
                             ah[mi][0], ah[mi][1], ah[mi][2], ah[mi][3], bl[ni][0], bl[ni][1]);
                }
        }
        __syncthreads();
    }

    const int tg = lane >> 2;
    const int tc = (lane & 3) * 2;
    #pragma unroll
    for (int ni = 0; ni < 4; ++ni) {
        const int col = n0 + wn + ni*8 + tc;
        const float bz0 = bias[col], bz1 = bias[col + 1];
        #pragma unroll
        for (int mi = 0; mi < 4; ++mi) {
            const int row = m0 + wm + mi*16 + tg;
            float v0 = acc[mi][ni][0] + bz0, v1 = acc[mi][ni][1] + bz1;
            float v2 = acc[mi][ni][2] + bz0, v3 = acc[mi][ni][3] + bz1;
            if (RELU) {
                v0 = fmaxf(v0, 0.f); v1 = fmaxf(v1, 0.f);
                v2 = fmaxf(v2, 0.f); v3 = fmaxf(v3, 0.f);
            }
            if (OMODE == 0) {
                *reinterpret_cast<float2*>(C + (size_t)row*N + col) = make_float2(v0, v1);
                *reinterpret_cast<float2*>(C + (size_t)(row + 8)*N + col) = make_float2(v2, v3);
            } else {
                uint32_t h0, l0, h1, l1;
                split_pack(v0, v1, h0, l0);
                split_pack(v2, v3, h1, l1);
                *reinterpret_cast<uint32_t*>(Chi + (size_t)row*N + col) = h0;
                *reinterpret_cast<uint32_t*>(Clo + (size_t)row*N + col) = l0;
                *reinterpret_cast<uint32_t*>(Chi + (size_t)(row + 8)*N + col) = h1;
                *reinterpret_cast<uint32_t*>(Clo + (size_t)(row + 8)*N + col) = l1;
            }
        }
    }
}

template<int OMODE, bool RELU>
__global__ void __launch_bounds__(256) mma_gemm_kernel(
    const __nv_bfloat16* __restrict__ Ahi, const __nv_bfloat16* __restrict__ Alo,
    const __nv_bfloat16* __restrict__ Bhi, const __nv_bfloat16* __restrict__ Blo,
    const float* __restrict__ bias, float* __restrict__ C,
    __nv_bfloat16* __restrict__ Chi, __nv_bfloat16* __restrict__ Clo,
    int M, int N, int K)
{
    mma_gemm_body<OMODE, RELU>(Ahi, Alo, Bhi, Blo, bias, C, Chi, Clo, M, N, K);
}

// QKV fused: split bf16 outputs for q,k,v
__global__ void __launch_bounds__(256) mma_gemm_qkv_kernel(
    const __nv_bfloat16* __restrict__ Ahi, const __nv_bfloat16* __restrict__ Alo,
    const __nv_bfloat16* __restrict__ Whi, const __nv_bfloat16* __restrict__ Wlo,
    const float* __restrict__ bq, const float* __restrict__ bk, const float* __restrict__ bv,
    __nv_bfloat16* __restrict__ qh, __nv_bfloat16* __restrict__ ql,
    __nv_bfloat16* __restrict__ kh, __nv_bfloat16* __restrict__ kl,
    __nv_bfloat16* __restrict__ vh, __nv_bfloat16* __restrict__ vl)
{
    const int z = blockIdx.z;
    const size_t woff = (size_t)z * DMODEL * DMODEL;
    const float* bias = (z == 0) ? bq : (z == 1) ? bk : bv;
    __nv_bfloat16* Chi = (z == 0) ? qh : (z == 1) ? kh : vh;
    __nv_bfloat16* Clo = (z == 0) ? ql : (z == 1) ? kl : vl;
    mma_gemm_body<1, false>(Ahi, Alo, Whi + woff, Wlo + woff, bias, nullptr,
                            Chi, Clo, NTOK, DMODEL, DMODEL);
}

// ---------------------------------------------------------------------------
// Weight transpose + split: W[K,N] fp32 -> Whi/Wlo[N,K] bf16. z = layer.
// ---------------------------------------------------------------------------
__global__ void wconv_t_kernel(const float* __restrict__ W, __nv_bfloat16* __restrict__ Whi,
                               __nv_bfloat16* __restrict__ Wlo, int K, int N,
                               size_t strideW, size_t strideO) {
    __shared__ float t[32][33];
    const int l = blockIdx.z;
    W += (size_t)l * strideW; Whi += (size_t)l * strideO; Wlo += (size_t)l * strideO;
    const int tx = threadIdx.x & 31, ty = threadIdx.x >> 5;
    const int kb = blockIdx.y * 32, nb = blockIdx.x * 32;
    #pragma unroll
    for (int i = ty; i < 32; i += 8)
        t[i][tx] = W[(size_t)(kb + i)*N + nb + tx];
    __syncthreads();
    #pragma unroll
    for (int i = ty; i < 32; i += 8) {
        float x = t[tx][i];
        __nv_bfloat16 h = __float2bfloat16(x);
        __nv_bfloat16 lo = __float2bfloat16(x - __bfloat162float(h));
        size_t o = (size_t)(nb + i)*K + kb + tx;
        Whi[o] = h; Wlo[o] = lo;
    }
}

// E split (all layers): fp32 -> hi/lo bf16
__global__ void econv_kernel(const float* __restrict__ E) {
    int i4 = blockIdx.x * blockDim.x + threadIdx.x;   // [0, L*SEQ*DHEAD/4)
    float4 x = reinterpret_cast<const float4*>(E)[i4];
    uint32_t h0, l0, h1, l1;
    split_pack(x.x, x.y, h0, l0);
    split_pack(x.z, x.w, h1, l1);
    reinterpret_cast<uint2*>(g_e_hi)[i4] = make_uint2(h0, h1);
    reinterpret_cast<uint2*>(g_e_lo)[i4] = make_uint2(l0, l1);
}

// ---------------------------------------------------------------------------
// Embedding: h = emb[x]*sqrt(D) + pos; also emit bf16 hi/lo split.
// ---------------------------------------------------------------------------
__global__ void embed_kernel(const int* __restrict__ x, const float* __restrict__ emb,
                             const float* __restrict__ pos) {
    int i4 = blockIdx.x * blockDim.x + threadIdx.x;
    int idx = i4 * 4;
    int t = idx >> 9;
    int d = idx & 511;
    int s = t & (SEQ-1);
    int tok = x[t];
    float4 e = *reinterpret_cast<const float4*>(&emb[(size_t)tok*DMODEL + d]);
    float4 p = *reinterpret_cast<const float4*>(&pos[(size_t)s*DMODEL + d]);
    float4 hv = make_float4(e.x*SQRT_D + p.x, e.y*SQRT_D + p.y,
                            e.z*SQRT_D + p.z, e.w*SQRT_D + p.w);
    *reinterpret_cast<float4*>(&g_h[idx]) = hv;
    uint32_t h0, l0, h1, l1;
    split_pack(hv.x, hv.y, h0, l0);
    split_pack(hv.z, hv.w, h1, l1);
    reinterpret_cast<uint2*>(g_h_hi)[i4] = make_uint2(h0, h1);
    reinterpret_cast<uint2*>(g_h_lo)[i4] = make_uint2(l0, l1);
}

// ---------------------------------------------------------------------------
// QE-skew on tensor cores. Inputs pre-split bf16 (qhi/qlo, ehi/elo).
// smem: Q hi/lo (64x144B each) + E hi/lo = 36864 B
// ---------------------------------------------------------------------------
#define TILE_B 9216      // 64 rows * 144 B
#define QE2_SMEM (4*TILE_B)

__global__ void __launch_bounds__(128) qe_skew2_kernel(
    const __nv_bfloat16* __restrict__ qhi, const __nv_bfloat16* __restrict__ qlo,
    const __nv_bfloat16* __restrict__ ehi, const __nv_bfloat16* __restrict__ elo,
    float* __restrict__ SK)
{
    extern __shared__ char smembuf[];
    const uint32_t sb = smem_u32(smembuf);

    const int bh = blockIdx.y;
    const int b  = bh >> 3;
    const int h  = bh & 7;
    const int i0 = blockIdx.x * 64;
    const int tid  = threadIdx.x;      // 128
    const int wid  = tid >> 5;
    const int lane = tid & 31;
    const int tok0 = b * SEQ;
    const int hoff = h * DHEAD;
    const int wq = wid * 16;
    const int koff16 = (lane >> 4) * 16;

    // load Q hi/lo tiles
    #pragma unroll
    for (int t = 0; t < 8; t++) {
        int idx = tid + t*128;                 // [0,1024)
        int op = idx >> 9, rem = idx & 511;
        int r = rem >> 3, g = rem & 7;
        const __nv_bfloat16* src = (op ? qlo : qhi) + (size_t)(tok0 + i0 + r)*DMODEL + hoff + g*8;
        cp_async16(sb + op*TILE_B + r*144 + g*16, src);
    }
    CP_COMMIT(); CP_WAIT(0);
    __syncthreads();

    // hoist Q fragments
    uint32_t ahq[4][4], alq[4][4];
    #pragma unroll
    for (int kt = 0; kt < 4; kt++) {
        uint32_t qa = sb + (wq + (lane & 15))*144 + kt*32 + koff16;
        ldm_x4(ahq[kt][0], ahq[kt][1], ahq[kt][2], ahq[kt][3], qa);
        ldm_x4(alq[kt][0], alq[kt][1], alq[kt][2], alq[kt][3], qa + TILE_B);
    }

    float* skb = SK + ((size_t)bh << 20);
    const int row0 = i0 + wq + (lane >> 2);
    const int qc = (lane & 3) * 2;
    const int mt_lo = ((960 - i0) >> 6) << 6;
    const uint32_t eb = sb + 2*TILE_B;

    for (int mt = mt_lo; mt < 1024; mt += 64) {
        __syncthreads();
        #pragma unroll
        for (int t = 0; t < 8; t++) {
            int idx = tid + t*128;
            int op = idx >> 9, rem = idx & 511;
            int r = rem >> 3, g = rem & 7;
            const __nv_bfloat16* src = (op ? elo : ehi) + (size_t)(mt + r)*DHEAD + g*8;
            cp_async16(eb + op*TILE_B + r*144 + g*16, src);
        }
        CP_COMMIT(); CP_WAIT(0);
        __syncthreads();

        float s[8][4];
        #pragma unroll
        for (int n = 0; n < 8; n++)
            #pragma unroll
            for (int e = 0; e < 4; e++) s[n][e] = 0.f;

        #pragma unroll
        for (int kt = 0; kt < 4; kt++) {
            uint32_t bh2[8][2], bl2[8][2];
            #pragma unroll
            for (int p = 0; p < 4; p++) {
                uint32_t r0, r1, r2, r3;
                uint32_t ba = eb + (p*16 + (lane & 15))*144 + kt*32 + koff16;
                ldm_x4(r0, r1, r2, r3, ba);
                bh2[2*p][0] = r0; bh2[2*p][1] = r2; bh2[2*p+1][0] = r1; bh2[2*p+1][1] = r3;
                ldm_x4(r0, r1, r2, r3, ba + TILE_B);
                bl2[2*p][0] = r0; bl2[2*p][1] = r2; bl2[2*p+1][0] = r1; bl2[2*p+1][1] = r3;
            }
            #pragma unroll
            for (int n = 0; n < 8; n++) {
                mma_bf16(s[n][0], s[n][1], s[n][2], s[n][3],
                         ahq[kt][0], ahq[kt][1], ahq[kt][2], ahq[kt][3], bh2[n][0], bh2[n][1]);
                mma_bf16(s[n][0], s[n][1], s[n][2], s[n][3],
                         alq[kt][0], alq[kt][1], alq[kt][2], alq[kt][3], bh2[n][0], bh2[n][1]);
                mma_bf16(s[n][0], s[n][1], s[n][2], s[n][3],
                         ahq[kt][0], ahq[kt][1], ahq[kt][2], ahq[kt][3], bl2[n][0], bl2[n][1]);
            }
        }

        // skewed scatter: QE[i][m] -> SK[i][j = m-1023+i]
        #pragma unroll
        for (int n = 0; n < 8; n++) {
            int m = mt + 8*n + qc;
            int j0 = m - 1023 + row0;
            if (j0 >= 0)       { skb[((size_t)row0 << 10) + j0] = s[n][0];
                                 skb[((size_t)row0 << 10) + j0 + 1] = s[n][1]; }
            else if (j0 == -1)   skb[((size_t)row0 << 10)] = s[n][1];
            int j1 = j0 + 8;
            int r1 = row0 + 8;
            if (j1 >= 0)       { skb[((size_t)r1 << 10) + j1] = s[n][2];
                                 skb[((size_t)r1 << 10) + j1 + 1] = s[n][3]; }
            else if (j1 == -1)   skb[((size_t)r1 << 10)] = s[n][3];
        }
    }
}

// ---------------------------------------------------------------------------
// Flash attention on tensor cores, pre-split bf16 inputs, double-buffered K/V,
// ldmatrix.trans for V. Writes bf16 hi/lo split output.
// smem: Q hi/lo + 2 stages x (Khi,Klo,Vhi,Vlo) = 2*9216 + 2*4*9216 = 92160 B
// ---------------------------------------------------------------------------
#define AT2_SMEM (2*TILE_B + 2*4*TILE_B)

__global__ void __launch_bounds__(128) attention2_kernel(
    const __nv_bfloat16* __restrict__ qhi, const __nv_bfloat16* __restrict__ qlo,
    const __nv_bfloat16* __restrict__ khi, const __nv_bfloat16* __restrict__ klo,
    const __nv_bfloat16* __restrict__ vhi, const __nv_bfloat16* __restrict__ vlo,
    const float* __restrict__ SK,
    __nv_bfloat16* __restrict__ Ohi, __nv_bfloat16* __restrict__ Olo)
{
    extern __shared__ char smembuf[];
    const uint32_t sb = smem_u32(smembuf);

    const int bh = blockIdx.y;
    const int b  = bh >> 3;
    const int h  = bh & 7;
    const int i0 = blockIdx.x * 64;
    const int tid  = threadIdx.x;      // 128
    const int wid  = tid >> 5;
    const int lane = tid & 31;
    const int tok0 = b * SEQ;
    const int hoff = h * DHEAD;
    const int wq = wid * 16;
    const int koff16 = (lane >> 4) * 16;

    auto load_kv = [&](int jt) {
        const int j0 = jt * 64;
        const uint32_t base = sb + 2*TILE_B + (jt & 1) * 4*TILE_B;
        #pragma unroll
        for (int t = 0; t < 16; t++) {
            int idx = tid + t*128;                 // [0,2048)
            int op = idx >> 9, rem = idx & 511;
            int r = rem >> 3, g = rem & 7;
            const __nv_bfloat16* src =
                (op == 0 ? khi : op == 1 ? klo : op == 2 ? vhi : vlo)
                + (size_t)(tok0 + j0 + r)*DMODEL + hoff + g*8;
            cp_async16(base + op*TILE_B + r*144 + g*16, src);
        }
        CP_COMMIT();
    };

    // Q tiles + first K/V as group 0
    #pragma unroll
    for (int t = 0; t < 8; t++) {
        int idx = tid + t*128;
        int op = idx >> 9, rem = idx & 511;
        int r = rem >> 3, g = rem & 7;
        const __nv_bfloat16* src = (op ? qlo : qhi) + (size_t)(tok0 + i0 + r)*DMODEL + hoff + g*8;
        cp_async16(sb + op*TILE_B + r*144 + g*16, src);
    }
    load_kv(0);

    float m_i[2] = {-1e30f, -1e30f}, l_i[2] = {0.f, 0.f};
    float acc[8][4];
    #pragma unroll
    for (int n = 0; n < 8; n++)
        #pragma unroll
        for (int e = 0; e < 4; e++) acc[n][e] = 0.f;

    const float* skb = SK + ((size_t)bh << 20);
    const int row0 = i0 + wq + (lane >> 2);
    const int qc = (lane & 3) * 2;

    uint32_t ahq[4][4], alq[4][4];

    for (int jt = 0; jt < 16; jt++) {
        const int j0 = jt * 64;
        if (jt + 1 < 16) { load_kv(jt + 1); CP_WAIT(1); }
        else             { CP_WAIT(0); }
        __syncthreads();

        const uint32_t kvb = sb + 2*TILE_B + (jt & 1) * 4*TILE_B;

        if (jt == 0) {
            #pragma unroll
            for (int kt = 0; kt < 4; kt++) {
                uint32_t qa = sb + (wq + (lane & 15))*144 + kt*32 + koff16;
                ldm_x4(ahq[kt][0], ahq[kt][1], ahq[kt][2], ahq[kt][3], qa);
                ldm_x4(alq[kt][0], alq[kt][1], alq[kt][2], alq[kt][3], qa + TILE_B);
            }
        }

        // ---- S = Q K^T (bf16x3) ----
        float s[8][4];
        #pragma unroll
        for (int n = 0; n < 8; n++)
            #pragma unroll
            for (int e = 0; e < 4; e++) s[n][e] = 0.f;

        #pragma unroll
        for (int kt = 0; kt < 4; kt++) {
            uint32_t bh2[8][2], bl2[8][2];
            #pragma unroll
            for (int p = 0; p < 4; p++) {
                uint32_t r0, r1, r2, r3;
                uint32_t ba = kvb + (p*16 + (lane & 15))*144 + kt*32 + koff16;
                ldm_x4(r0, r1, r2, r3, ba);
                bh2[2*p][0] = r0; bh2[2*p][1] = r2; bh2[2*p+1][0] = r1; bh2[2*p+1][1] = r3;
                ldm_x4(r0, r1, r2, r3, ba + TILE_B);
                bl2[2*p][0] = r0; bl2[2*p][1] = r2; bl2[2*p+1][0] = r1; bl2[2*p+1][1] = r3;
            }
            #pragma unroll
            for (int n = 0; n < 8; n++) {
                mma_bf16(s[n][0], s[n][1], s[n][2], s[n][3],
                         ahq[kt][0], ahq[kt][1], ahq[kt][2], ahq[kt][3], bh2[n][0], bh2[n][1]);
                mma_bf16(s[n][0], s[n][1], s[n][2], s[n][3],
                         alq[kt][0], alq[kt][1], alq[kt][2], alq[kt][3], bh2[n][0], bh2[n][1]);
                mma_bf16(s[n][0], s[n][1], s[n][2], s[n][3],
                         ahq[kt][0], ahq[kt][1], ahq[kt][2], ahq[kt][3], bl2[n][0], bl2[n][1]);
            }
        }

        // ---- rel term + scale ----
        #pragma unroll
        for (int n = 0; n < 8; n++) {
            int jc = j0 + 8*n + qc;
            const float* p0 = skb + ((size_t)row0 << 10) + jc;
            const float* p1 = p0 + (8 << 10);
            if (jc     <= row0)     s[n][0] += p0[0];
            if (jc + 1 <= row0)     s[n][1] += p0[1];
            if (jc     <= row0 + 8) s[n][2] += p1[0];
            if (jc + 1 <= row0 + 8) s[n][3] += p1[1];
            #pragma unroll
            for (int e = 0; e < 4; e++) s[n][e] *= INV_SQRT_DH;
        }

        // ---- online softmax ----
        #pragma unroll
        for (int rr = 0; rr < 2; rr++) {
            float mx = -1e30f;
            #pragma unroll
            for (int n = 0; n < 8; n++) {
                mx = fmaxf(mx, s[n][2*rr]);
                mx = fmaxf(mx, s[n][2*rr + 1]);
            }
            mx = fmaxf(mx, __shfl_xor_sync(0xffffffffu, mx, 1));
            mx = fmaxf(mx, __shfl_xor_sync(0xffffffffu, mx, 2));
            float mn = fmaxf(m_i[rr], mx);
            float alpha = __expf(m_i[rr] - mn);
            float ps = 0.f;
            #pragma unroll
            for (int n = 0; n < 8; n++) {
                float p0 = __expf(s[n][2*rr]     - mn);
                float p1 = __expf(s[n][2*rr + 1] - mn);
                s[n][2*rr] = p0; s[n][2*rr + 1] = p1;
                ps += p0 + p1;
            }
            ps += __shfl_xor_sync(0xffffffffu, ps, 1);
            ps += __shfl_xor_sync(0xffffffffu, ps, 2);
            l_i[rr] = l_i[rr] * alpha + ps;
            m_i[rr] = mn;
            #pragma unroll
            for (int dn = 0; dn < 8; dn++) {
                acc[dn][2*rr]     *= alpha;
                acc[dn][2*rr + 1] *= alpha;
            }
        }

        // ---- pack P ----
        uint32_t ph[8][2], pl[8][2];
        #pragma unroll
        for (int n = 0; n < 8; n++) {
            split_pack(s[n][0], s[n][1], ph[n][0], pl[n][0]);
            split_pack(s[n][2], s[n][3], ph[n][1], pl[n][1]);
        }

        // ---- O += P V (V via ldmatrix.trans) ----
        const uint32_t vb = kvb + 2*TILE_B;
        #pragma unroll
        for (int kt = 0; kt < 4; kt++) {
            uint32_t ah0 = ph[2*kt][0], ah1 = ph[2*kt][1], ah2 = ph[2*kt+1][0], ah3 = ph[2*kt+1][1];
            uint32_t al0 = pl[2*kt][0], al1 = pl[2*kt][1], al2 = pl[2*kt+1][0], al3 = pl[2*kt+1][1];
            uint32_t vh2[8][2], vl2[8][2];
            #pragma unroll
            for (int p = 0; p < 4; p++) {
                uint32_t r0, r1, r2, r3;
                uint32_t va = vb + (kt*16 + (lane & 15))*144 + p*32 + koff16;
                ldm_x4t(r0, r1, r2, r3, va);
                vh2[2*p][0] = r0; vh2[2*p][1] = r1; vh2[2*p+1][0] = r2; vh2[2*p+1][1] = r3;
                ldm_x4t(r0, r1, r2, r3, va + TILE_B);
                vl2[2*p][0] = r0; vl2[2*p][1] = r1; vl2[2*p+1][0] = r2; vl2[2*p+1][1] = r3;
            }
            #pragma unroll
            for (int dn = 0; dn < 8; dn++) {
                mma_bf16(acc[dn][0], acc[dn][1], acc[dn][2], acc[dn][3],
                         ah0, ah1, ah2, ah3, vh2[dn][0], vh2[dn][1]);
                mma_bf16(acc[dn][0], acc[dn][1], acc[dn][2], acc[dn][3],
                         al0, al1, al2, al3, vh2[dn][0], vh2[dn][1]);
                mma_bf16(acc[dn][0], acc[dn][1], acc[dn][2], acc[dn][3],
                         ah0, ah1, ah2, ah3, vl2[dn][0], vl2[dn][1]);
            }
        }
        __syncthreads();
    }

    // normalize + split-store
    #pragma unroll
    for (int rr = 0; rr < 2; rr++) {
        float inv = 1.f / l_i[rr];
        int row = row0 + rr*8;
        #pragma unroll
        for (int dn = 0; dn < 8; dn++) {
            float o0 = acc[dn][2*rr] * inv, o1 = acc[dn][2*rr + 1] * inv;
            uint32_t hi, lo;
            split_pack(o0, o1, hi, lo);
            size_t oaddr = (size_t)(tok0 + row)*DMODEL + hoff + 8*dn + qc;
            *reinterpret_cast<uint32_t*>(Ohi + oaddr) = hi;
            *reinterpret_cast<uint32_t*>(Olo + oaddr) = lo;
        }
    }
}

// ---------------------------------------------------------------------------
// y = LayerNorm(a + b) * scale + bias; emits fp32 y and bf16 hi/lo split.
// ---------------------------------------------------------------------------
__global__ void add_ln_kernel(const float* __restrict__ a, const float* __restrict__ b,
                              const float* __restrict__ scale, const float* __restrict__ bias,
                              float* __restrict__ y,
                              __nv_bfloat16* __restrict__ yhi, __nv_bfloat16* __restrict__ ylo) {
    const int t = blockIdx.x;
    const int tid = threadIdx.x;       // 128
    const int d4 = tid * 4;
    const size_t base = (size_t)t*DMODEL + d4;
    float4 av = *reinterpret_cast<const float4*>(a + base);
    float4 bv = *reinterpret_cast<const float4*>(b + base);
    float x[4] = {av.x + bv.x, av.y + bv.y, av.z + bv.z, av.w + bv.w};
    float sum = x[0] + x[1] + x[2] + x[3];
    __shared__ float red[4];
    #pragma unroll
    for (int o = 16; o > 0; o >>= 1) sum += __shfl_xor_sync(0xffffffffu, sum, o);
    if ((tid & 31) == 0) red[tid >> 5] = sum;
    __syncthreads();
    sum = red[0] + red[1] + red[2] + red[3];
    const float mu = sum * (1.f/512.f);
    float vs = 0.f;
    #pragma unroll
    for (int i = 0; i < 4; i++) { float dd = x[i] - mu; vs = fmaf(dd, dd, vs); }
    #pragma unroll
    for (int o = 16; o > 0; o >>= 1) vs += __shfl_xor_sync(0xffffffffu, vs, o);
    __shared__ float red2[4];
    if ((tid & 31) == 0) red2[tid >> 5] = vs;
    __syncthreads();
    vs = red2[0] + red2[1] + red2[2] + red2[3];
    const float rstd = rsqrtf(vs * (1.f/512.f) + 1e-6f);
    float o[4];
    #pragma unroll
    for (int i = 0; i < 4; i++)
        o[i] = (x[i] - mu) * rstd * scale[d4 + i] + bias[d4 + i];
    *reinterpret_cast<float4*>(y + base) = make_float4(o[0], o[1], o[2], o[3]);
    uint32_t h0, l0, h1, l1;
    split_pack(o[0], o[1], h0, l0);
    split_pack(o[2], o[3], h1, l1);
    *reinterpret_cast<uint2*>(yhi + base) = make_uint2(h0, h1);
    *reinterpret_cast<uint2*>(ylo + base) = make_uint2(l0, l1);
}

// ---------------------------------------------------------------------------
// out[b,o] = tanh(h[b,0,:] . Wf[:,o] + bf[o])
// ---------------------------------------------------------------------------
__global__ void head_kernel(const float* __restrict__ Wf, const float* __restrict__ bf,
                            float* __restrict__ out) {
    const int w = threadIdx.x >> 5;
    const int lane = threadIdx.x & 31;
    const int b = w >> 1, o = w & 1;
    const float* hr = g_h + (size_t)b*SEQ*DMODEL;
    float sum = 0.f;
    #pragma unroll
    for (int d = lane; d < DMODEL; d += 32)
        sum = fmaf(hr[d], Wf[d*2 + o], sum);
    #pragma unroll
    for (int off = 16; off > 0; off >>= 1) sum += __shfl_xor_sync(0xffffffffu, sum, off);
    if (lane == 0) out[b*2 + o] = tanhf(sum + bf[o]);
}

// ---------------------------------------------------------------------------
// Launch
// ---------------------------------------------------------------------------
extern "C" void kernel_launch(void* const* d_in, const int* in_sizes, int n_in,
                              void* d_out, int out_size) {
    const int*   x    = (const int*)  d_in[0];
    const float* emb  = (const float*)d_in[1];
    const float* pos  = (const float*)d_in[2];
    const float* Wq   = (const float*)d_in[3];
    const float* bq   = (const float*)d_in[4];
    const float* Wk   = (const float*)d_in[5];
    const float* bk   = (const float*)d_in[6];
    const float* Wv   = (const float*)d_in[7];
    const float* bv   = (const float*)d_in[8];
    const float* Wo   = (const float*)d_in[9];
    const float* bo   = (const float*)d_in[10];
    const float* E    = (const float*)d_in[11];
    const float* W1   = (const float*)d_in[12];
    const float* b1   = (const float*)d_in[13];
    const float* W2   = (const float*)d_in[14];
    const float* b2   = (const float*)d_in[15];
    const float* ln1s = (const float*)d_in[16];
    const float* ln1b = (const float*)d_in[17];
    const float* ln2s = (const float*)d_in[18];
    const float* ln2b = (const float*)d_in[19];
    const float* Wf   = (const float*)d_in[20];
    const float* bf   = (const float*)d_in[21];
    float* out = (float*)d_out;

    float *h, *h1, *ffn, *sk;
    cudaGetSymbolAddress((void**)&h,   g_h);
    cudaGetSymbolAddress((void**)&h1,  g_h1);
    cudaGetSymbolAddress((void**)&ffn, g_ffn);
    cudaGetSymbolAddress((void**)&sk,  g_sk);

    __nv_bfloat16 *hhi, *hlo, *qh, *ql, *kh, *kl, *vh, *vl;
    __nv_bfloat16 *athi, *atlo, *h1hi, *h1lo, *mdhi, *mdlo, *ehi, *elo;
    __nv_bfloat16 *w4h, *w4l, *w1h, *w1l, *w2h, *w2l;
    cudaGetSymbolAddress((void**)&hhi,  g_h_hi);
    cudaGetSymbolAddress((void**)&hlo,  g_h_lo);
    cudaGetSymbolAddress((void**)&qh,   g_q_hi);
    cudaGetSymbolAddress((void**)&ql,   g_q_lo);
    cudaGetSymbolAddress((void**)&kh,   g_k_hi);
    cudaGetSymbolAddress((void**)&kl,   g_k_lo);
    cudaGetSymbolAddress((void**)&vh,   g_v_hi);
    cudaGetSymbolAddress((void**)&vl,   g_v_lo);
    cudaGetSymbolAddress((void**)&athi, g_attn_hi);
    cudaGetSymbolAddress((void**)&atlo, g_attn_lo);
    cudaGetSymbolAddress((void**)&h1hi, g_h1_hi);
    cudaGetSymbolAddress((void**)&h1lo, g_h1_lo);
    cudaGetSymbolAddress((void**)&mdhi, g_mid_hi);
    cudaGetSymbolAddress((void**)&mdlo, g_mid_lo);
    cudaGetSymbolAddress((void**)&ehi,  g_e_hi);
    cudaGetSymbolAddress((void**)&elo,  g_e_lo);
    cudaGetSymbolAddress((void**)&w4h, g_w4_hi);
    cudaGetSymbolAddress((void**)&w4l, g_w4_lo);
    cudaGetSymbolAddress((void**)&w1h, g_w1_hi);
    cudaGetSymbolAddress((void**)&w1l, g_w1_lo);
    cudaGetSymbolAddress((void**)&w2h, g_w2_hi);
    cudaGetSymbolAddress((void**)&w2l, g_w2_lo);

    cudaFuncSetAttribute(attention2_kernel, cudaFuncAttributeMaxDynamicSharedMemorySize, AT2_SMEM);
    cudaFuncSetAttribute(qe_skew2_kernel,   cudaFuncAttributeMaxDynamicSharedMemorySize, QE2_SMEM);
    cudaFuncSetAttribute((const void*)mma_gemm_kernel<0,false>, cudaFuncAttributeMaxDynamicSharedMemorySize, MMA_SMEM);
    cudaFuncSetAttribute((const void*)mma_gemm_kernel<1,true>,  cudaFuncAttributeMaxDynamicSharedMemorySize, MMA_SMEM);
    cudaFuncSetAttribute((const void*)mma_gemm_qkv_kernel,      cudaFuncAttributeMaxDynamicSharedMemorySize, MMA_SMEM);

    const size_t SZ = (size_t)DMODEL * DMODEL;      // 262144

    wconv_t_kernel<<<dim3(16,16,NLAYER), 256>>>(Wq, w4h + 0*SZ, w4l + 0*SZ, DMODEL, DMODEL, SZ, 4*SZ);
    wconv_t_kernel<<<dim3(16,16,NLAYER), 256>>>(Wk, w4h + 1*SZ, w4l + 1*SZ, DMODEL, DMODEL, SZ, 4*SZ);
    wconv_t_kernel<<<dim3(16,16,NLAYER), 256>>>(Wv, w4h + 2*SZ, w4l + 2*SZ, DMODEL, DMODEL, SZ, 4*SZ);
    wconv_t_kernel<<<dim3(16,16,NLAYER), 256>>>(Wo, w4h + 3*SZ, w4l + 3*SZ, DMODEL, DMODEL, SZ, 4*SZ);
    wconv_t_kernel<<<dim3(64,16,NLAYER), 256>>>(W1, w1h, w1l, DMODEL, DINNER,
                                                (size_t)DMODEL*DINNER, (size_t)DINNER*DMODEL);
    wconv_t_kernel<<<dim3(16,64,NLAYER), 256>>>(W2, w2h, w2l, DINNER, DMODEL,
                                                (size_t)DINNER*DMODEL, (size_t)DMODEL*DINNER);
    econv_kernel<<<NLAYER*SEQ*DHEAD/4/256, 256>>>(E);

    embed_kernel<<<NTOK*DMODEL/4/256, 256>>>(x, emb, pos);

    for (int l = 0; l < NLAYER; l++) {
        const __nv_bfloat16* l4h = w4h + (size_t)l*4*SZ;
        const __nv_bfloat16* l4l = w4l + (size_t)l*4*SZ;

        mma_gemm_qkv_kernel<<<dim3(4,32,3), 256, MMA_SMEM>>>(hhi, hlo, l4h, l4l,
            bq + l*DMODEL, bk + l*DMODEL, bv + l*DMODEL, qh, ql, kh, kl, vh, vl);

        qe_skew2_kernel<<<dim3(16,32), 128, QE2_SMEM>>>(qh, ql,
            ehi + (size_t)l*SEQ*DHEAD, elo + (size_t)l*SEQ*DHEAD, sk);
        attention2_kernel<<<dim3(16,32), 128, AT2_SMEM>>>(qh, ql, kh, kl, vh, vl, sk, athi, atlo);

        mma_gemm_kernel<0,false><<<dim3(4,32), 256, MMA_SMEM>>>(athi, atlo, l4h + 3*SZ, l4l + 3*SZ,
            bo + l*DMODEL, ffn, nullptr, nullptr, NTOK, DMODEL, DMODEL);
        add_ln_kernel<<<NTOK, 128>>>(ffn, h, ln1s + l*DMODEL, ln1b + l*DMODEL, h1, h1hi, h1lo);

        mma_gemm_kernel<1,true><<<dim3(16,32), 256, MMA_SMEM>>>(h1hi, h1lo,
            w1h + (size_t)l*DINNER*DMODEL, w1l + (size_t)l*DINNER*DMODEL,
            b1 + l*DINNER, nullptr, mdhi, mdlo, NTOK, DINNER, DMODEL);

        mma_gemm_kernel<0,false><<<dim3(4,32), 256, MMA_SMEM>>>(mdhi, mdlo,
            w2h + (size_t)l*DMODEL*DINNER, w2l + (size_t)l*DMODEL*DINNER,
            b2 + l*DMODEL, ffn, nullptr, nullptr, NTOK, DMODEL, DINNER);
        add_ln_kernel<<<NTOK, 128>>>(h1, ffn, ln2s + l*DMODEL, ln2b + l*DMODEL, h, hhi, hlo);
    }

    head_kernel<<<1, 256>>>(Wf, bf, out);
}